// round 5
// baseline (speedup 1.0000x reference)
#include <cuda_runtime.h>
#include <math.h>
#include <stdint.h>

#define BB 1024
#define DD 512
#define KK 255
#define LL 256
#define CC 80
#define NGRP 16

#define XPART 16384      // 128 rows x 128B (one ks chunk, one part)
#define WPART 10240      // 80 rows x 128B

// ---- smem layout (bytes) ----
#define SM_X   0                 // [ks 0..3][part 0..1][16384] = 131072
#define SM_W   131072            // 4 bufs x 2 parts x 10240 = 81920
#define SM_PS  212992            // 128*17*4 = 8704
#define SM_BS  221696            // 16*80*4 = 5120
#define SM_MB  226816            // mbarriers
#define SMEM_MAIN 226944

// ---------------- device scratch ----------------
__device__ float g_ne[KK * DD];
__device__ float g_probs[BB * LL];
__device__ float g_partial[NGRP * BB * CC];
__device__ __align__(16) uint8_t g_xb[(size_t)8 * 8 * XPART];        // [rt][ks*2+part][16384] swizzled
__device__ __align__(16) uint8_t g_wb[(size_t)LL * 4 * 2 * WPART];   // [leaf][ks][part][10240] swizzled

// ---------------- helpers ----------------
__device__ __forceinline__ uint32_t s2u(const void* p) {
    uint32_t a;
    asm("{ .reg .u64 t; cvta.to.shared.u64 t, %1; cvt.u32.u64 %0, t; }" : "=r"(a) : "l"(p));
    return a;
}
#define MBINIT(m, c)  asm volatile("mbarrier.init.shared.b64 [%0], %1;" :: "r"(m), "r"(c) : "memory")
#define MBEXPECT(m, b) asm volatile("mbarrier.arrive.expect_tx.shared.b64 _, [%0], %1;" :: "r"(m), "r"(b) : "memory")
#define MBARRIVE(m)   asm volatile("mbarrier.arrive.shared.b64 _, [%0];" :: "r"(m) : "memory")
__device__ __forceinline__ void mbwait(uint32_t m, uint32_t ph) {
    asm volatile(
        "{\n .reg .pred P;\n"
        "LW_%=:\n mbarrier.try_wait.parity.acquire.cta.shared::cta.b64 P, [%0], %1, 0x989680;\n"
        " @P bra LD_%=;\n bra LW_%=;\nLD_%=:\n}"
        :: "r"(m), "r"(ph) : "memory");
}
#define BULK(dst, src, sz, mb) \
    asm volatile("cp.async.bulk.shared::cta.global.mbarrier::complete_tx::bytes [%0], [%1], %2, [%3];" \
                 :: "r"(dst), "l"(src), "r"(sz), "r"(mb) : "memory")

__device__ __forceinline__ void ldsm4(uint32_t* r, uint32_t a) {
    asm volatile("ldmatrix.sync.aligned.m8n8.x4.shared.b16 {%0,%1,%2,%3}, [%4];"
        : "=r"(r[0]), "=r"(r[1]), "=r"(r[2]), "=r"(r[3]) : "r"(a));
}
__device__ __forceinline__ void ldsm2(uint32_t* r, uint32_t a) {
    asm volatile("ldmatrix.sync.aligned.m8n8.x2.shared.b16 {%0,%1}, [%2];"
        : "=r"(r[0]), "=r"(r[1]) : "r"(a));
}
__device__ __forceinline__ void mma_s8(int* c, const uint32_t* a, const uint32_t* b) {
    asm volatile(
        "mma.sync.aligned.m16n8k32.row.col.s32.s8.s8.s32 "
        "{%0,%1,%2,%3}, {%4,%5,%6,%7}, {%8,%9}, {%0,%1,%2,%3};"
        : "+r"(c[0]), "+r"(c[1]), "+r"(c[2]), "+r"(c[3])
        : "r"(a[0]), "r"(a[1]), "r"(a[2]), "r"(a[3]), "r"(b[0]), "r"(b[1]));
}

// ---------------- K1: normalize node embeddings ----------------
__global__ void k_norm(const float* __restrict__ ne) {
    int k = blockIdx.x;
    int t = threadIdx.x;
    const float* row = ne + (size_t)k * DD;
    float s = 0.f;
    for (int d = t; d < DD; d += 128) { float v = row[d]; s += v * v; }
    __shared__ float red[4];
    #pragma unroll
    for (int o = 16; o > 0; o >>= 1) s += __shfl_xor_sync(0xffffffffu, s, o);
    if ((t & 31) == 0) red[t >> 5] = s;
    __syncthreads();
    float inv = 1.0f / sqrtf(red[0] + red[1] + red[2] + red[3]);
    for (int d = t; d < DD; d += 128) g_ne[(size_t)k * DD + d] = row[d] * inv;
}

// ---------------- K2: node_sim = sigmoid(x @ ne^T) ----------------
__global__ void k_nodesim(const float* __restrict__ x, float* __restrict__ out_ns) {
    __shared__ float xt[64 * 32];
    __shared__ float nt[64 * 36];
    int row0 = blockIdx.x * 64;
    int col0 = blockIdx.y * 64;
    int tid = threadIdx.x;
    int tx = tid & 15, ty = tid >> 4;
    float acc[4][4] = {};
    for (int dk = 0; dk < 16; ++dk) {
        #pragma unroll
        for (int i = 0; i < 2; ++i) {
            int idx = tid + i * 256;
            int r = idx >> 3, dg = idx & 7;
            float4 v = *(const float4*)(x + (size_t)(row0 + r) * DD + dk * 32 + dg * 4);
            *(float4*)(xt + r * 32 + dg * 4) = v;
        }
        #pragma unroll
        for (int i = 0; i < 2; ++i) {
            int idx = tid + i * 256;
            int r = idx >> 3, dg = idx & 7;
            int kk = col0 + r;
            float4 v = make_float4(0.f, 0.f, 0.f, 0.f);
            if (kk < KK) v = *(const float4*)(g_ne + (size_t)kk * DD + dk * 32 + dg * 4);
            *(float4*)(nt + r * 36 + dg * 4) = v;
        }
        __syncthreads();
        #pragma unroll
        for (int k = 0; k < 32; ++k) {
            float xf[4], nf[4];
            #pragma unroll
            for (int i = 0; i < 4; ++i) xf[i] = xt[(ty * 4 + i) * 32 + k];
            #pragma unroll
            for (int j = 0; j < 4; ++j) nf[j] = nt[(tx + 16 * j) * 36 + k];
            #pragma unroll
            for (int i = 0; i < 4; ++i)
                #pragma unroll
                for (int j = 0; j < 4; ++j) acc[i][j] += xf[i] * nf[j];
        }
        __syncthreads();
    }
    #pragma unroll
    for (int i = 0; i < 4; ++i)
        #pragma unroll
        for (int j = 0; j < 4; ++j) {
            int r = row0 + ty * 4 + i, c = col0 + tx + 16 * j;
            if (c < KK) out_ns[(size_t)r * KK + c] = 1.0f / (1.0f + expf(-acc[i][j]));
        }
}

// ---------------- K3: leaf probabilities ----------------
__global__ void k_probs(const float* __restrict__ ns) {
    int b = blockIdx.x;
    int leaf = threadIdx.x;
    __shared__ float s[KK];
    if (leaf < KK) s[leaf] = ns[(size_t)b * KK + leaf];
    __syncthreads();
    float p = 1.0f; int node = 0;
    #pragma unroll
    for (int d = 0; d < 8; ++d) {
        int bit = (leaf >> (7 - d)) & 1;
        float v = s[node];
        p *= bit ? (1.0f - v) : v;
        node = 2 * node + 1 + bit;
    }
    g_probs[(size_t)b * LL + leaf] = p;
}

// ---------------- int8 conversion kernels ----------------
// x = (a*128 + b) * 2^-11 : a = rint(x*16), b = rint((x - a/16)*2048)
__global__ void k_convX(const float* __restrict__ x) {
    int t = blockIdx.x * 256 + threadIdx.x;   // 1024*32
    int row = t >> 5, c16 = t & 31;
    int ks = c16 >> 3, cc = c16 & 7;
    int rt = row >> 7, r = row & 127;
    const float4* src = (const float4*)(x + (size_t)row * 512 + c16 * 16);
    uint32_t hi[4], lo[4];
    #pragma unroll
    for (int j = 0; j < 4; ++j) {
        float4 v = src[j];
        float vv[4] = {v.x, v.y, v.z, v.w};
        uint32_t h = 0, l = 0;
        #pragma unroll
        for (int i = 0; i < 4; ++i) {
            int a = __float2int_rn(vv[i] * 16.f);
            a = a > 127 ? 127 : (a < -127 ? -127 : a);
            float rr = vv[i] - (float)a * 0.0625f;
            int b = __float2int_rn(rr * 2048.f);
            b = b > 127 ? 127 : (b < -127 ? -127 : b);
            h |= (uint32_t)(a & 255) << (8 * i);
            l |= (uint32_t)(b & 255) << (8 * i);
        }
        hi[j] = h; lo[j] = l;
    }
    size_t base = ((size_t)(rt * 4 + ks)) * 2 * XPART + r * 128 + ((uint32_t)(cc ^ (r & 7)) << 4);
    *(uint4*)(g_xb + base) = make_uint4(hi[0], hi[1], hi[2], hi[3]);
    *(uint4*)(g_xb + base + XPART) = make_uint4(lo[0], lo[1], lo[2], lo[3]);
}

// w = (c*128 + d) * 2^-16 : c = rint(w*512), d = rint((w - c/512)*65536)
__global__ void k_convW(const float* __restrict__ W) {
    int t = blockIdx.x * 256 + threadIdx.x;   // 20480*32
    int row = t >> 5, c16 = t & 31;
    int ks = c16 >> 3, cc = c16 & 7;
    int l = row / 80, n = row - l * 80;
    const float4* src = (const float4*)(W + (size_t)row * 512 + c16 * 16);
    uint32_t hi[4], lo[4];
    #pragma unroll
    for (int j = 0; j < 4; ++j) {
        float4 v = src[j];
        float vv[4] = {v.x, v.y, v.z, v.w};
        uint32_t h = 0, lw = 0;
        #pragma unroll
        for (int i = 0; i < 4; ++i) {
            int c = __float2int_rn(vv[i] * 512.f);
            c = c > 127 ? 127 : (c < -127 ? -127 : c);
            float rr = vv[i] - (float)c * 0.001953125f;
            int d = __float2int_rn(rr * 65536.f);
            d = d > 127 ? 127 : (d < -127 ? -127 : d);
            h |= (uint32_t)(c & 255) << (8 * i);
            lw |= (uint32_t)(d & 255) << (8 * i);
        }
        hi[j] = h; lo[j] = lw;
    }
    size_t base = ((size_t)(l * 4 + ks)) * 2 * WPART + n * 128 + ((uint32_t)(cc ^ (n & 7)) << 4);
    *(uint4*)(g_wb + base) = make_uint4(hi[0], hi[1], hi[2], hi[3]);
    *(uint4*)(g_wb + base + WPART) = make_uint4(lo[0], lo[1], lo[2], lo[3]);
}

// ---------------- K5: main IMMA kernel ----------------
// grid (8 rowtiles, 16 leaf-groups), 256 threads = 8 warps (4 M x 2 N).
// leaf outer (0..15), ks inner (0..3). X fully resident; W ring of 4.
__global__ void __launch_bounds__(256, 1) k_main(const float* __restrict__ bias) {
    extern __shared__ char smem[];
    const uint32_t sb = s2u(smem);
    const int tid = threadIdx.x;
    const int rt = blockIdx.x, grp = blockIdx.y;
    const int wid = tid >> 5, lane = tid & 31;
    const int wm = wid >> 1, wn = wid & 1;
    const int lr = lane >> 2, lc = lane & 3;

    const uint32_t MB = sb + SM_MB;
    #define WFULL(b)  (MB + (b) * 8)
    #define WEMPTY(b) (MB + 32 + (b) * 8)
    #define XFULL     (MB + 64)

    if (tid == 0) {
        for (int b = 0; b < 4; ++b) { MBINIT(WFULL(b), 1); MBINIT(WEMPTY(b), 8); }
        MBINIT(XFULL, 1);
    }
    float* psm = (float*)(smem + SM_PS);
    float* bsm = (float*)(smem + SM_BS);
    for (int j = tid; j < 128 * 16; j += 256) {
        int r = j >> 4, l = j & 15;
        psm[r * 17 + l] = g_probs[(size_t)(rt * 128 + r) * LL + grp * 16 + l];
    }
    for (int j = tid; j < 16 * CC; j += 256) bsm[j] = bias[grp * 16 * CC + j];
    __syncthreads();

    // prologue: X (all 8 chunks) + W stages 0..2
    if (tid == 0) {
        MBEXPECT(XFULL, 8 * XPART);
        #pragma unroll
        for (int j = 0; j < 8; ++j)
            BULK(sb + SM_X + j * XPART, g_xb + ((size_t)rt * 8 + j) * XPART, XPART, XFULL);
        #pragma unroll
        for (int s = 0; s < 3; ++s) {
            MBEXPECT(WFULL(s), 2 * WPART);
            BULK(sb + SM_W + s * 2 * WPART,
                 g_wb + ((size_t)((grp * 16 + (s >> 2)) * 4 + (s & 3))) * 2 * WPART,
                 2 * WPART, WFULL(s));
        }
    }

    // per-thread fragment addressing (bytes within a part)
    const int rx = lane & 7;
    const uint32_t aA0 = (uint32_t)(wm * 32 + ((lane >> 3) & 1) * 8 + rx) * 128;
    const uint32_t aA1 = aA0 + 16 * 128;
    const int ao16 = (lane >> 4) & 1;
    const uint32_t bB0 = (uint32_t)(wn * 40 + ((lane >> 4) & 1) * 8 + rx) * 128;
    const uint32_t bB1 = bB0 + 16 * 128;
    const int bo16 = (lane >> 3) & 1;
    const int l16 = lane & 15;
    const uint32_t bB2 = (uint32_t)(wn * 40 + 32 + (l16 & 7)) * 128;
    const int bo2 = (l16 >> 3) & 1;
    const int rx2 = l16 & 7;

    // init per with bias term: per = sum_l p[row,l] * bias[l,col]
    float per[2][5][4];
    #pragma unroll
    for (int mt = 0; mt < 2; ++mt)
        #pragma unroll
        for (int nt = 0; nt < 5; ++nt)
            per[mt][nt][0] = per[mt][nt][1] = per[mt][nt][2] = per[mt][nt][3] = 0.f;
    for (int l = 0; l < 16; ++l) {
        float pv[2][2];
        #pragma unroll
        for (int mt = 0; mt < 2; ++mt) {
            pv[mt][0] = psm[(wm * 32 + mt * 16 + lr) * 17 + l];
            pv[mt][1] = psm[(wm * 32 + mt * 16 + 8 + lr) * 17 + l];
        }
        #pragma unroll
        for (int nt = 0; nt < 5; ++nt) {
            int c0 = wn * 40 + nt * 8 + lc * 2;
            float b0 = bsm[l * CC + c0], b1 = bsm[l * CC + c0 + 1];
            #pragma unroll
            for (int mt = 0; mt < 2; ++mt) {
                per[mt][nt][0] = fmaf(pv[mt][0], b0, per[mt][nt][0]);
                per[mt][nt][1] = fmaf(pv[mt][0], b1, per[mt][nt][1]);
                per[mt][nt][2] = fmaf(pv[mt][1], b0, per[mt][nt][2]);
                per[mt][nt][3] = fmaf(pv[mt][1], b1, per[mt][nt][3]);
            }
        }
    }

    mbwait(XFULL, 0);   // X resident

    int hh[2][5][4] = {}, mid[2][5][4] = {};
    int cwf[4] = {0, 0, 0, 0}, pwe[4] = {0, 0, 0, 0};

    for (int lf = 0; lf < 16; ++lf) {
        for (int ks = 0; ks < 4; ++ks) {
            const int s = lf * 4 + ks, buf = s & 3;

            if (tid == 0) {
                int sn = s + 3;
                if (sn < 64) {
                    int bn = sn & 3;
                    if (sn >= 4) { mbwait(WEMPTY(bn), pwe[bn] & 1); pwe[bn]++; }
                    MBEXPECT(WFULL(bn), 2 * WPART);
                    BULK(sb + SM_W + bn * 2 * WPART,
                         g_wb + ((size_t)((grp * 16 + (sn >> 2)) * 4 + (sn & 3))) * 2 * WPART,
                         2 * WPART, WFULL(bn));
                }
            }

            mbwait(WFULL(buf), cwf[buf] & 1); cwf[buf]++;
            const uint32_t xks = sb + SM_X + ks * (2 * XPART);
            const uint32_t wb_ = sb + SM_W + buf * (2 * WPART);

            #pragma unroll
            for (int kc = 0; kc < 4; ++kc) {
                const uint32_t swA = (uint32_t)((((kc << 1) | ao16) ^ rx) << 4);
                const uint32_t swB = (uint32_t)((((kc << 1) | bo16) ^ rx) << 4);
                const uint32_t swB2 = (uint32_t)((((kc << 1) | bo2) ^ rx2) << 4);
                uint32_t ah[2][4], al[2][4], bh[5][2], bl[5][2];
                ldsm4(ah[0], xks + aA0 + swA);
                ldsm4(ah[1], xks + aA1 + swA);
                ldsm4(al[0], xks + XPART + aA0 + swA);
                ldsm4(al[1], xks + XPART + aA1 + swA);
                ldsm4(&bh[0][0], wb_ + bB0 + swB);
                ldsm4(&bh[2][0], wb_ + bB1 + swB);
                ldsm2(&bh[4][0], wb_ + bB2 + swB2);
                ldsm4(&bl[0][0], wb_ + WPART + bB0 + swB);
                ldsm4(&bl[2][0], wb_ + WPART + bB1 + swB);
                ldsm2(&bl[4][0], wb_ + WPART + bB2 + swB2);
                #pragma unroll
                for (int mt = 0; mt < 2; ++mt)
                    #pragma unroll
                    for (int nt = 0; nt < 5; ++nt) {
                        mma_s8(hh[mt][nt], ah[mt], bh[nt]);
                        mma_s8(mid[mt][nt], ah[mt], bl[nt]);
                        mma_s8(mid[mt][nt], al[mt], bh[nt]);
                    }
            }

            if (lane == 0) MBARRIVE(WEMPTY(buf));

            if (ks == 3) {
                // fold: out += p * 2^-13 * (hh + mid * 2^-7)
                #pragma unroll
                for (int mt = 0; mt < 2; ++mt) {
                    float p0 = psm[(wm * 32 + mt * 16 + lr) * 17 + lf] * 1.220703125e-4f;
                    float p1 = psm[(wm * 32 + mt * 16 + 8 + lr) * 17 + lf] * 1.220703125e-4f;
                    #pragma unroll
                    for (int nt = 0; nt < 5; ++nt) {
                        float t0 = fmaf((float)mid[mt][nt][0], 0.0078125f, (float)hh[mt][nt][0]);
                        float t1 = fmaf((float)mid[mt][nt][1], 0.0078125f, (float)hh[mt][nt][1]);
                        float t2 = fmaf((float)mid[mt][nt][2], 0.0078125f, (float)hh[mt][nt][2]);
                        float t3 = fmaf((float)mid[mt][nt][3], 0.0078125f, (float)hh[mt][nt][3]);
                        per[mt][nt][0] = fmaf(p0, t0, per[mt][nt][0]);
                        per[mt][nt][1] = fmaf(p0, t1, per[mt][nt][1]);
                        per[mt][nt][2] = fmaf(p1, t2, per[mt][nt][2]);
                        per[mt][nt][3] = fmaf(p1, t3, per[mt][nt][3]);
                        hh[mt][nt][0] = hh[mt][nt][1] = hh[mt][nt][2] = hh[mt][nt][3] = 0;
                        mid[mt][nt][0] = mid[mt][nt][1] = mid[mt][nt][2] = mid[mt][nt][3] = 0;
                    }
                }
            }
        }
    }

    float* base = g_partial + (size_t)grp * BB * CC;
    #pragma unroll
    for (int mt = 0; mt < 2; ++mt) {
        int r0 = rt * 128 + wm * 32 + mt * 16 + lr;
        #pragma unroll
        for (int nt = 0; nt < 5; ++nt) {
            int c0 = wn * 40 + nt * 8 + lc * 2;
            *(float2*)(base + (size_t)r0 * CC + c0) = make_float2(per[mt][nt][0], per[mt][nt][1]);
            *(float2*)(base + (size_t)(r0 + 8) * CC + c0) = make_float2(per[mt][nt][2], per[mt][nt][3]);
        }
    }
}

// ---------------- K6: reduce partials ----------------
__global__ void k_reduce(float* __restrict__ out) {
    int idx = blockIdx.x * 256 + threadIdx.x;
    float s = 0.f;
    #pragma unroll
    for (int g = 0; g < NGRP; ++g)
        s += g_partial[(size_t)g * BB * CC + idx];
    out[idx] = s;
}

// ---------------- launch ----------------
extern "C" void kernel_launch(void* const* d_in, const int* in_sizes, int n_in,
                              void* d_out, int out_size) {
    const float* x    = (const float*)d_in[0];
    const float* ne   = (const float*)d_in[1];
    const float* W    = (const float*)d_in[2];
    const float* bias = (const float*)d_in[3];

    float* out1 = (float*)d_out;
    float* ns   = (float*)d_out + BB * CC;

    cudaFuncSetAttribute(k_main, cudaFuncAttributeMaxDynamicSharedMemorySize, SMEM_MAIN);

    k_norm<<<KK, 128>>>(ne);
    dim3 g2(BB / 64, 4);
    k_nodesim<<<g2, 256>>>(x, ns);
    k_probs<<<BB, 256>>>(ns);
    k_convW<<<2560, 256>>>(W);
    k_convX<<<128, 256>>>(x);
    dim3 g5(8, NGRP);
    k_main<<<g5, 256, SMEM_MAIN>>>(bias);
    k_reduce<<<(BB * CC) / 256, 256>>>(out1);
}

// round 6
// speedup vs baseline: 2.9573x; 2.9573x over previous
#include <cuda_runtime.h>
#include <cuda_fp16.h>
#include <math.h>
#include <stdint.h>

#define BB 1024
#define DD 512
#define KK 255
#define LL 256
#define CC 80
#define NGRP 16

#define WCH 11520      // W chunk: 80 rows x 144B (fp16 hi only)
#define XCH 18432      // X chunk per part: 128 rows x 144B

// ---- smem layout (bytes) ----
#define SM_X   0                     // 2 bufs x 2 parts x 18432 = 73728
#define SM_W   73728                 // 3 bufs x 11520 = 34560
#define SM_PS  108288                // 128*17*4 = 8704
#define SM_BS  116992                // 16*80*4 = 5120
#define SM_MB  122112                // mbarriers (80B)
#define SMEM_MAIN 122240

// ---------------- device scratch ----------------
__device__ float g_ne[KK * DD];
__device__ float g_probs[BB * LL];
__device__ float g_partial[NGRP * BB * CC];
__device__ __align__(16) uint8_t g_wb[(size_t)LL * 8 * WCH];      // [leaf][ks][80x144B] fp16 hi
__device__ __align__(16) uint8_t g_xb[(size_t)8 * 8 * 2 * XCH];   // [rt][ks][part][128x144B] fp16

// ---------------- helpers ----------------
__device__ __forceinline__ uint32_t s2u(const void* p) {
    uint32_t a;
    asm("{ .reg .u64 t; cvta.to.shared.u64 t, %1; cvt.u32.u64 %0, t; }" : "=r"(a) : "l"(p));
    return a;
}
#define MBINIT(m, c)  asm volatile("mbarrier.init.shared.b64 [%0], %1;" :: "r"(m), "r"(c) : "memory")
#define MBEXPECT(m, b) asm volatile("mbarrier.arrive.expect_tx.shared.b64 _, [%0], %1;" :: "r"(m), "r"(b) : "memory")
#define MBARRIVE(m)   asm volatile("mbarrier.arrive.shared.b64 _, [%0];" :: "r"(m) : "memory")
__device__ __forceinline__ void mbwait(uint32_t m, uint32_t ph) {
    asm volatile(
        "{\n .reg .pred P;\n"
        "LW_%=:\n mbarrier.try_wait.parity.acquire.cta.shared::cta.b64 P, [%0], %1, 0x989680;\n"
        " @P bra LD_%=;\n bra LW_%=;\nLD_%=:\n}"
        :: "r"(m), "r"(ph) : "memory");
}
#define BULK(dst, src, sz, mb) \
    asm volatile("cp.async.bulk.shared::cta.global.mbarrier::complete_tx::bytes [%0], [%1], %2, [%3];" \
                 :: "r"(dst), "l"(src), "r"(sz), "r"(mb) : "memory")

__device__ __forceinline__ void ldsm4(uint32_t* r, uint32_t a) {
    asm volatile("ldmatrix.sync.aligned.m8n8.x4.shared.b16 {%0,%1,%2,%3}, [%4];"
        : "=r"(r[0]), "=r"(r[1]), "=r"(r[2]), "=r"(r[3]) : "r"(a));
}
__device__ __forceinline__ void ldsm2(uint32_t* r, uint32_t a) {
    asm volatile("ldmatrix.sync.aligned.m8n8.x2.shared.b16 {%0,%1}, [%2];"
        : "=r"(r[0]), "=r"(r[1]) : "r"(a));
}
__device__ __forceinline__ void mma_f16(float* c, const uint32_t* a, const uint32_t* b) {
    asm volatile(
        "mma.sync.aligned.m16n8k16.row.col.f32.f16.f16.f32 "
        "{%0,%1,%2,%3}, {%4,%5,%6,%7}, {%8,%9}, {%0,%1,%2,%3};"
        : "+f"(c[0]), "+f"(c[1]), "+f"(c[2]), "+f"(c[3])
        : "r"(a[0]), "r"(a[1]), "r"(a[2]), "r"(a[3]), "r"(b[0]), "r"(b[1]));
}

// ---------------- K1: normalize node embeddings ----------------
__global__ void k_norm(const float* __restrict__ ne) {
    int k = blockIdx.x;
    int t = threadIdx.x;
    const float* row = ne + (size_t)k * DD;
    float s = 0.f;
    for (int d = t; d < DD; d += 128) { float v = row[d]; s += v * v; }
    __shared__ float red[4];
    #pragma unroll
    for (int o = 16; o > 0; o >>= 1) s += __shfl_xor_sync(0xffffffffu, s, o);
    if ((t & 31) == 0) red[t >> 5] = s;
    __syncthreads();
    float inv = 1.0f / sqrtf(red[0] + red[1] + red[2] + red[3]);
    for (int d = t; d < DD; d += 128) g_ne[(size_t)k * DD + d] = row[d] * inv;
}

// ---------------- K2: node_sim = sigmoid(x @ ne^T) ----------------
__global__ void k_nodesim(const float* __restrict__ x, float* __restrict__ out_ns) {
    __shared__ float xt[64 * 32];
    __shared__ float nt[64 * 36];
    int row0 = blockIdx.x * 64;
    int col0 = blockIdx.y * 64;
    int tid = threadIdx.x;
    int tx = tid & 15, ty = tid >> 4;
    float acc[4][4] = {};
    for (int dk = 0; dk < 16; ++dk) {
        #pragma unroll
        for (int i = 0; i < 2; ++i) {
            int idx = tid + i * 256;
            int r = idx >> 3, dg = idx & 7;
            float4 v = *(const float4*)(x + (size_t)(row0 + r) * DD + dk * 32 + dg * 4);
            *(float4*)(xt + r * 32 + dg * 4) = v;
        }
        #pragma unroll
        for (int i = 0; i < 2; ++i) {
            int idx = tid + i * 256;
            int r = idx >> 3, dg = idx & 7;
            int kk = col0 + r;
            float4 v = make_float4(0.f, 0.f, 0.f, 0.f);
            if (kk < KK) v = *(const float4*)(g_ne + (size_t)kk * DD + dk * 32 + dg * 4);
            *(float4*)(nt + r * 36 + dg * 4) = v;
        }
        __syncthreads();
        #pragma unroll
        for (int k = 0; k < 32; ++k) {
            float xf[4], nf[4];
            #pragma unroll
            for (int i = 0; i < 4; ++i) xf[i] = xt[(ty * 4 + i) * 32 + k];
            #pragma unroll
            for (int j = 0; j < 4; ++j) nf[j] = nt[(tx + 16 * j) * 36 + k];
            #pragma unroll
            for (int i = 0; i < 4; ++i)
                #pragma unroll
                for (int j = 0; j < 4; ++j) acc[i][j] += xf[i] * nf[j];
        }
        __syncthreads();
    }
    #pragma unroll
    for (int i = 0; i < 4; ++i)
        #pragma unroll
        for (int j = 0; j < 4; ++j) {
            int r = row0 + ty * 4 + i, c = col0 + tx + 16 * j;
            if (c < KK) out_ns[(size_t)r * KK + c] = 1.0f / (1.0f + expf(-acc[i][j]));
        }
}

// ---------------- K3: leaf probabilities ----------------
__global__ void k_probs(const float* __restrict__ ns) {
    int b = blockIdx.x;
    int leaf = threadIdx.x;
    __shared__ float s[KK];
    if (leaf < KK) s[leaf] = ns[(size_t)b * KK + leaf];
    __syncthreads();
    float p = 1.0f; int node = 0;
    #pragma unroll
    for (int d = 0; d < 8; ++d) {
        int bit = (leaf >> (7 - d)) & 1;
        float v = s[node];
        p *= bit ? (1.0f - v) : v;
        node = 2 * node + 1 + bit;
    }
    g_probs[(size_t)b * LL + leaf] = p;
}

// ---------------- conversion kernels ----------------
// W: fp16 hi only.  [l*80+n][512] -> g_wb[leaf*8+ks][n*144 + k*2]
__global__ void k_convW(const float* __restrict__ W) {
    int t = blockIdx.x * 256 + threadIdx.x;      // 20480*64
    int row = t >> 6;
    int kg = t & 63;
    int leaf = row / 80, n = row - leaf * 80;
    int ks = kg >> 3, k8 = kg & 7;
    float4 a = *(const float4*)(W + (size_t)row * 512 + kg * 8);
    float4 b = *(const float4*)(W + (size_t)row * 512 + kg * 8 + 4);
    float v[8] = {a.x, a.y, a.z, a.w, b.x, b.y, b.z, b.w};
    unsigned short hb[8];
    #pragma unroll
    for (int i = 0; i < 8; ++i) hb[i] = __half_as_ushort(__float2half_rn(v[i]));
    uint4 HI = make_uint4(((uint32_t)hb[1] << 16) | hb[0], ((uint32_t)hb[3] << 16) | hb[2],
                          ((uint32_t)hb[5] << 16) | hb[4], ((uint32_t)hb[7] << 16) | hb[6]);
    *(uint4*)(g_wb + (size_t)(leaf * 8 + ks) * WCH + n * 144 + k8 * 16) = HI;
}
// X: fp16 hi + lo (residual). [row][512] -> g_xb[(rt*8+ks)*2+part][r*144 + k*2]
__global__ void k_convX(const float* __restrict__ x) {
    int t = blockIdx.x * 256 + threadIdx.x;      // 1024*64
    int row = t >> 6;
    int kg = t & 63;
    int rt = row >> 7, r = row & 127;
    int ks = kg >> 3, k8 = kg & 7;
    float4 a = *(const float4*)(x + (size_t)row * 512 + kg * 8);
    float4 b = *(const float4*)(x + (size_t)row * 512 + kg * 8 + 4);
    float v[8] = {a.x, a.y, a.z, a.w, b.x, b.y, b.z, b.w};
    unsigned short hb[8], lb[8];
    #pragma unroll
    for (int i = 0; i < 8; ++i) {
        __half h = __float2half_rn(v[i]);
        hb[i] = __half_as_ushort(h);
        lb[i] = __half_as_ushort(__float2half_rn(v[i] - __half2float(h)));
    }
    uint8_t* dst = g_xb + (size_t)(rt * 8 + ks) * 2 * XCH + r * 144 + k8 * 16;
    *(uint4*)dst = make_uint4(((uint32_t)hb[1] << 16) | hb[0], ((uint32_t)hb[3] << 16) | hb[2],
                              ((uint32_t)hb[5] << 16) | hb[4], ((uint32_t)hb[7] << 16) | hb[6]);
    *(uint4*)(dst + XCH) = make_uint4(((uint32_t)lb[1] << 16) | lb[0], ((uint32_t)lb[3] << 16) | lb[2],
                                      ((uint32_t)lb[5] << 16) | lb[4], ((uint32_t)lb[7] << 16) | lb[6]);
}

// ---------------- K5: main HMMA kernel (fp16 2-term) ----------------
// grid (8 rowtiles, 16 leaf-groups), 256 threads = 8 warps (4 M x 2 N).
// Stage s (0..127): ks = s>>4 (k-chunk of 64), leaf = s&15.
__global__ void __launch_bounds__(256, 1) k_main(const float* __restrict__ bias) {
    extern __shared__ char smem[];
    const uint32_t sb = s2u(smem);
    const int tid = threadIdx.x;
    const int rt = blockIdx.x, grp = blockIdx.y;
    const int wid = tid >> 5, lane = tid & 31;
    const int wm = wid >> 1, wn = wid & 1;
    const int lr = lane >> 2, lc = lane & 3;

    const uint32_t MB = sb + SM_MB;
    #define WFULL(b)  (MB + (b) * 8)
    #define WEMPTY(b) (MB + 24 + (b) * 8)
    #define XFULL(b)  (MB + 48 + (b) * 8)
    #define XEMPTY(b) (MB + 64 + (b) * 8)

    if (tid == 0) {
        for (int b = 0; b < 3; ++b) { MBINIT(WFULL(b), 1); MBINIT(WEMPTY(b), 8); }
        for (int b = 0; b < 2; ++b) { MBINIT(XFULL(b), 1); MBINIT(XEMPTY(b), 8); }
    }
    float* psm = (float*)(smem + SM_PS);
    float* bsm = (float*)(smem + SM_BS);
    for (int j = tid; j < 128 * 16; j += 256) {
        int r = j >> 4, l = j & 15;
        psm[r * 17 + l] = g_probs[(size_t)(rt * 128 + r) * LL + grp * 16 + l];
    }
    for (int j = tid; j < 16 * CC; j += 256) bsm[j] = bias[grp * 16 * CC + j];
    __syncthreads();

    // prologue: W stages 0,1 ; X ks 0
    if (tid == 0) {
        #pragma unroll
        for (int s = 0; s < 2; ++s) {
            MBEXPECT(WFULL(s), WCH);
            BULK(sb + SM_W + s * WCH,
                 g_wb + (size_t)((grp * 16 + s) * 8 + 0) * WCH, WCH, WFULL(s));
        }
        MBEXPECT(XFULL(0), 2 * XCH);
        BULK(sb + SM_X, g_xb + (size_t)(rt * 8 + 0) * 2 * XCH, 2 * XCH, XFULL(0));
    }

    // per-thread invariant ldmatrix offsets (bytes within part)
    const uint32_t aoff0 = (uint32_t)(wm * 32 + ((lane >> 3) & 1) * 8 + (lane & 7)) * 144
                           + ((lane >> 4) & 1) * 16;
    const uint32_t aoff1 = aoff0 + 16 * 144;
    const uint32_t boff0 = (uint32_t)(wn * 40 + ((lane >> 4) & 1) * 8 + (lane & 7)) * 144
                           + ((lane >> 3) & 1) * 16;
    const uint32_t boff1 = boff0 + 16 * 144;
    const int l16 = lane & 15;
    const uint32_t boff2 = (uint32_t)(wn * 40 + 32 + (l16 & 7)) * 144 + ((l16 >> 3) & 1) * 16;

    float per[2][5][4] = {};
    int cwf[3] = {0, 0, 0}, cxf[2] = {0, 0};
    int pwe[3] = {0, 0, 0}, pxe[2] = {0, 0};

    for (int s = 0; s < 128; ++s) {
        const int b = s % 3;
        const int ks = s >> 4, leaf = s & 15;
        const int xb = ks & 1;

        if (tid == 0) {
            int sn = s + 2;
            if (sn < 128) {
                int bn = sn % 3;
                if (sn >= 3) { mbwait(WEMPTY(bn), pwe[bn] & 1); pwe[bn]++; }
                MBEXPECT(WFULL(bn), WCH);
                int lf = grp * 16 + (sn & 15), kn = sn >> 4;
                BULK(sb + SM_W + bn * WCH,
                     g_wb + (size_t)(lf * 8 + kn) * WCH, WCH, WFULL(bn));
            }
            if (leaf == 8 && ks + 1 < 8) {
                int kn = ks + 1, xbn = kn & 1;
                if (kn >= 2) { mbwait(XEMPTY(xbn), pxe[xbn] & 1); pxe[xbn]++; }
                MBEXPECT(XFULL(xbn), 2 * XCH);
                BULK(sb + SM_X + xbn * (2 * XCH),
                     g_xb + (size_t)(rt * 8 + kn) * 2 * XCH, 2 * XCH, XFULL(xbn));
            }
        }

        mbwait(WFULL(b), cwf[b] & 1); cwf[b]++;
        if (leaf == 0) { mbwait(XFULL(xb), cxf[xb] & 1); cxf[xb]++; }

        float acc[2][5][4];
        if (ks == 0) {
            #pragma unroll
            for (int nt = 0; nt < 5; ++nt) {
                int c0 = wn * 40 + nt * 8 + lc * 2;
                float b0 = bsm[leaf * CC + c0], b1 = bsm[leaf * CC + c0 + 1];
                #pragma unroll
                for (int mt = 0; mt < 2; ++mt) {
                    acc[mt][nt][0] = b0; acc[mt][nt][1] = b1;
                    acc[mt][nt][2] = b0; acc[mt][nt][3] = b1;
                }
            }
        } else {
            #pragma unroll
            for (int mt = 0; mt < 2; ++mt)
                #pragma unroll
                for (int nt = 0; nt < 5; ++nt)
                    acc[mt][nt][0] = acc[mt][nt][1] = acc[mt][nt][2] = acc[mt][nt][3] = 0.f;
        }

        const uint32_t xh = sb + SM_X + xb * (2 * XCH);
        const uint32_t xl = xh + XCH;
        const uint32_t wh = sb + SM_W + b * WCH;

        #pragma unroll
        for (int kc = 0; kc < 4; ++kc) {
            const int ko = kc * 32;
            uint32_t ah[2][4], al[2][4], bh[5][2];
            ldsm4(ah[0], xh + aoff0 + ko);
            ldsm4(ah[1], xh + aoff1 + ko);
            ldsm4(al[0], xl + aoff0 + ko);
            ldsm4(al[1], xl + aoff1 + ko);
            ldsm4(&bh[0][0], wh + boff0 + ko);
            ldsm4(&bh[2][0], wh + boff1 + ko);
            ldsm2(&bh[4][0], wh + boff2 + ko);
            #pragma unroll
            for (int mt = 0; mt < 2; ++mt)
                #pragma unroll
                for (int nt = 0; nt < 5; ++nt) {
                    mma_f16(acc[mt][nt], ah[mt], bh[nt]);
                    mma_f16(acc[mt][nt], al[mt], bh[nt]);
                }
        }

        // fold probability (linearity: out = sum over chunks of p * chunk)
        #pragma unroll
        for (int mt = 0; mt < 2; ++mt) {
            float p0 = psm[(wm * 32 + mt * 16 + lr) * 17 + leaf];
            float p1 = psm[(wm * 32 + mt * 16 + 8 + lr) * 17 + leaf];
            #pragma unroll
            for (int nt = 0; nt < 5; ++nt) {
                per[mt][nt][0] = fmaf(p0, acc[mt][nt][0], per[mt][nt][0]);
                per[mt][nt][1] = fmaf(p0, acc[mt][nt][1], per[mt][nt][1]);
                per[mt][nt][2] = fmaf(p1, acc[mt][nt][2], per[mt][nt][2]);
                per[mt][nt][3] = fmaf(p1, acc[mt][nt][3], per[mt][nt][3]);
            }
        }

        if (lane == 0) {
            MBARRIVE(WEMPTY(b));
            if (leaf == 15) MBARRIVE(XEMPTY(xb));
        }
    }

    float* base = g_partial + (size_t)grp * BB * CC;
    #pragma unroll
    for (int mt = 0; mt < 2; ++mt) {
        int r0 = rt * 128 + wm * 32 + mt * 16 + lr;
        #pragma unroll
        for (int nt = 0; nt < 5; ++nt) {
            int c0 = wn * 40 + nt * 8 + lc * 2;
            *(float2*)(base + (size_t)r0 * CC + c0) = make_float2(per[mt][nt][0], per[mt][nt][1]);
            *(float2*)(base + (size_t)(r0 + 8) * CC + c0) = make_float2(per[mt][nt][2], per[mt][nt][3]);
        }
    }
}

// ---------------- K6: reduce partials ----------------
__global__ void k_reduce(float* __restrict__ out) {
    int idx = blockIdx.x * 256 + threadIdx.x;
    float s = 0.f;
    #pragma unroll
    for (int g = 0; g < NGRP; ++g)
        s += g_partial[(size_t)g * BB * CC + idx];
    out[idx] = s;
}

// ---------------- launch ----------------
extern "C" void kernel_launch(void* const* d_in, const int* in_sizes, int n_in,
                              void* d_out, int out_size) {
    const float* x    = (const float*)d_in[0];
    const float* ne   = (const float*)d_in[1];
    const float* W    = (const float*)d_in[2];
    const float* bias = (const float*)d_in[3];

    float* out1 = (float*)d_out;
    float* ns   = (float*)d_out + BB * CC;

    cudaFuncSetAttribute(k_main, cudaFuncAttributeMaxDynamicSharedMemorySize, SMEM_MAIN);

    k_norm<<<KK, 128>>>(ne);
    dim3 g2(BB / 64, 4);
    k_nodesim<<<g2, 256>>>(x, ns);
    k_probs<<<BB, 256>>>(ns);
    k_convW<<<5120, 256>>>(W);
    k_convX<<<256, 256>>>(x);
    dim3 g5(8, NGRP);
    k_main<<<g5, 256, SMEM_MAIN>>>(bias);
    k_reduce<<<(BB * CC) / 256, 256>>>(out1);
}

// round 7
// speedup vs baseline: 3.8378x; 1.2977x over previous
#include <cuda_runtime.h>
#include <cuda_fp16.h>
#include <math.h>
#include <stdint.h>

#define BB 1024
#define DD 512
#define KK 255
#define LL 256
#define CC 80
#define NGRP 16

#define WCH 11520      // W chunk: 80 rows x 144B (fp16)
#define XCH 18432      // X chunk: 128 rows x 144B (fp16)

// ---- smem layout (bytes) ----
#define SM_X   0                     // 2 bufs x 18432 = 36864
#define SM_W   36864                 // 3 bufs x 11520 = 34560
#define SM_PS  71424                 // 128*17*4 = 8704
#define SM_BS  80128                 // 16*80*4 = 5120
#define SM_MB  85248                 // mbarriers (80B)
#define SMEM_MAIN 85376

// ---------------- device scratch ----------------
__device__ float g_ne[KK * DD];
__device__ float g_probs[BB * LL];
__device__ float g_partial[NGRP * BB * CC];
__device__ __align__(16) uint8_t g_wb[(size_t)LL * 8 * WCH];   // [leaf][ks][80x144B] fp16
__device__ __align__(16) uint8_t g_xb[(size_t)8 * 8 * XCH];    // [rt][ks][128x144B] fp16

// ---------------- helpers ----------------
__device__ __forceinline__ uint32_t s2u(const void* p) {
    uint32_t a;
    asm("{ .reg .u64 t; cvta.to.shared.u64 t, %1; cvt.u32.u64 %0, t; }" : "=r"(a) : "l"(p));
    return a;
}
#define MBINIT(m, c)  asm volatile("mbarrier.init.shared.b64 [%0], %1;" :: "r"(m), "r"(c) : "memory")
#define MBEXPECT(m, b) asm volatile("mbarrier.arrive.expect_tx.shared.b64 _, [%0], %1;" :: "r"(m), "r"(b) : "memory")
#define MBARRIVE(m)   asm volatile("mbarrier.arrive.shared.b64 _, [%0];" :: "r"(m) : "memory")
__device__ __forceinline__ void mbwait(uint32_t m, uint32_t ph) {
    asm volatile(
        "{\n .reg .pred P;\n"
        "LW_%=:\n mbarrier.try_wait.parity.acquire.cta.shared::cta.b64 P, [%0], %1, 0x989680;\n"
        " @P bra LD_%=;\n bra LW_%=;\nLD_%=:\n}"
        :: "r"(m), "r"(ph) : "memory");
}
#define BULK(dst, src, sz, mb) \
    asm volatile("cp.async.bulk.shared::cta.global.mbarrier::complete_tx::bytes [%0], [%1], %2, [%3];" \
                 :: "r"(dst), "l"(src), "r"(sz), "r"(mb) : "memory")

__device__ __forceinline__ void ldsm4(uint32_t* r, uint32_t a) {
    asm volatile("ldmatrix.sync.aligned.m8n8.x4.shared.b16 {%0,%1,%2,%3}, [%4];"
        : "=r"(r[0]), "=r"(r[1]), "=r"(r[2]), "=r"(r[3]) : "r"(a));
}
__device__ __forceinline__ void ldsm2(uint32_t* r, uint32_t a) {
    asm volatile("ldmatrix.sync.aligned.m8n8.x2.shared.b16 {%0,%1}, [%2];"
        : "=r"(r[0]), "=r"(r[1]) : "r"(a));
}
__device__ __forceinline__ void mma_f16(float* c, const uint32_t* a, const uint32_t* b) {
    asm volatile(
        "mma.sync.aligned.m16n8k16.row.col.f32.f16.f16.f32 "
        "{%0,%1,%2,%3}, {%4,%5,%6,%7}, {%8,%9}, {%0,%1,%2,%3};"
        : "+f"(c[0]), "+f"(c[1]), "+f"(c[2]), "+f"(c[3])
        : "r"(a[0]), "r"(a[1]), "r"(a[2]), "r"(a[3]), "r"(b[0]), "r"(b[1]));
}

// ---------------- K1: normalize node embeddings ----------------
__global__ void k_norm(const float* __restrict__ ne) {
    int k = blockIdx.x;
    int t = threadIdx.x;
    const float* row = ne + (size_t)k * DD;
    float s = 0.f;
    for (int d = t; d < DD; d += 128) { float v = row[d]; s += v * v; }
    __shared__ float red[4];
    #pragma unroll
    for (int o = 16; o > 0; o >>= 1) s += __shfl_xor_sync(0xffffffffu, s, o);
    if ((t & 31) == 0) red[t >> 5] = s;
    __syncthreads();
    float inv = 1.0f / sqrtf(red[0] + red[1] + red[2] + red[3]);
    for (int d = t; d < DD; d += 128) g_ne[(size_t)k * DD + d] = row[d] * inv;
}

// ---------------- K2: node_sim = sigmoid(x @ ne^T) ----------------
__global__ void k_nodesim(const float* __restrict__ x, float* __restrict__ out_ns) {
    __shared__ float xt[64 * 32];
    __shared__ float nt[64 * 36];
    int row0 = blockIdx.x * 64;
    int col0 = blockIdx.y * 64;
    int tid = threadIdx.x;
    int tx = tid & 15, ty = tid >> 4;
    float acc[4][4] = {};
    for (int dk = 0; dk < 16; ++dk) {
        #pragma unroll
        for (int i = 0; i < 2; ++i) {
            int idx = tid + i * 256;
            int r = idx >> 3, dg = idx & 7;
            float4 v = *(const float4*)(x + (size_t)(row0 + r) * DD + dk * 32 + dg * 4);
            *(float4*)(xt + r * 32 + dg * 4) = v;
        }
        #pragma unroll
        for (int i = 0; i < 2; ++i) {
            int idx = tid + i * 256;
            int r = idx >> 3, dg = idx & 7;
            int kk = col0 + r;
            float4 v = make_float4(0.f, 0.f, 0.f, 0.f);
            if (kk < KK) v = *(const float4*)(g_ne + (size_t)kk * DD + dk * 32 + dg * 4);
            *(float4*)(nt + r * 36 + dg * 4) = v;
        }
        __syncthreads();
        #pragma unroll
        for (int k = 0; k < 32; ++k) {
            float xf[4], nf[4];
            #pragma unroll
            for (int i = 0; i < 4; ++i) xf[i] = xt[(ty * 4 + i) * 32 + k];
            #pragma unroll
            for (int j = 0; j < 4; ++j) nf[j] = nt[(tx + 16 * j) * 36 + k];
            #pragma unroll
            for (int i = 0; i < 4; ++i)
                #pragma unroll
                for (int j = 0; j < 4; ++j) acc[i][j] += xf[i] * nf[j];
        }
        __syncthreads();
    }
    #pragma unroll
    for (int i = 0; i < 4; ++i)
        #pragma unroll
        for (int j = 0; j < 4; ++j) {
            int r = row0 + ty * 4 + i, c = col0 + tx + 16 * j;
            if (c < KK) out_ns[(size_t)r * KK + c] = 1.0f / (1.0f + expf(-acc[i][j]));
        }
}

// ---------------- K3: leaf probabilities ----------------
__global__ void k_probs(const float* __restrict__ ns) {
    int b = blockIdx.x;
    int leaf = threadIdx.x;
    __shared__ float s[KK];
    if (leaf < KK) s[leaf] = ns[(size_t)b * KK + leaf];
    __syncthreads();
    float p = 1.0f; int node = 0;
    #pragma unroll
    for (int d = 0; d < 8; ++d) {
        int bit = (leaf >> (7 - d)) & 1;
        float v = s[node];
        p *= bit ? (1.0f - v) : v;
        node = 2 * node + 1 + bit;
    }
    g_probs[(size_t)b * LL + leaf] = p;
}

// ---------------- conversion kernels ----------------
__global__ void k_convW(const float* __restrict__ W) {
    int t = blockIdx.x * 256 + threadIdx.x;      // 20480*64
    int row = t >> 6;
    int kg = t & 63;
    int leaf = row / 80, n = row - leaf * 80;
    int ks = kg >> 3, k8 = kg & 7;
    float4 a = *(const float4*)(W + (size_t)row * 512 + kg * 8);
    float4 b = *(const float4*)(W + (size_t)row * 512 + kg * 8 + 4);
    float v[8] = {a.x, a.y, a.z, a.w, b.x, b.y, b.z, b.w};
    unsigned short hb[8];
    #pragma unroll
    for (int i = 0; i < 8; ++i) hb[i] = __half_as_ushort(__float2half_rn(v[i]));
    uint4 HI = make_uint4(((uint32_t)hb[1] << 16) | hb[0], ((uint32_t)hb[3] << 16) | hb[2],
                          ((uint32_t)hb[5] << 16) | hb[4], ((uint32_t)hb[7] << 16) | hb[6]);
    *(uint4*)(g_wb + (size_t)(leaf * 8 + ks) * WCH + n * 144 + k8 * 16) = HI;
}
__global__ void k_convX(const float* __restrict__ x) {
    int t = blockIdx.x * 256 + threadIdx.x;      // 1024*64
    int row = t >> 6;
    int kg = t & 63;
    int rt = row >> 7, r = row & 127;
    int ks = kg >> 3, k8 = kg & 7;
    float4 a = *(const float4*)(x + (size_t)row * 512 + kg * 8);
    float4 b = *(const float4*)(x + (size_t)row * 512 + kg * 8 + 4);
    float v[8] = {a.x, a.y, a.z, a.w, b.x, b.y, b.z, b.w};
    unsigned short hb[8];
    #pragma unroll
    for (int i = 0; i < 8; ++i) hb[i] = __half_as_ushort(__float2half_rn(v[i]));
    *(uint4*)(g_xb + (size_t)(rt * 8 + ks) * XCH + r * 144 + k8 * 16) =
        make_uint4(((uint32_t)hb[1] << 16) | hb[0], ((uint32_t)hb[3] << 16) | hb[2],
                   ((uint32_t)hb[5] << 16) | hb[4], ((uint32_t)hb[7] << 16) | hb[6]);
}

// ---------------- K5: main HMMA kernel (fp16 single-term, A hoisted) ----------------
// grid (8 rowtiles, 16 leaf-groups), 256 threads = 8 warps (4 M x 2 N).
// Stage s (0..127): ks = s>>4 (k-chunk of 64), leaf = s&15.
__global__ void __launch_bounds__(256, 1) k_main(const float* __restrict__ bias) {
    extern __shared__ char smem[];
    const uint32_t sb = s2u(smem);
    const int tid = threadIdx.x;
    const int rt = blockIdx.x, grp = blockIdx.y;
    const int wid = tid >> 5, lane = tid & 31;
    const int wm = wid >> 1, wn = wid & 1;
    const int lr = lane >> 2, lc = lane & 3;

    const uint32_t MB = sb + SM_MB;
    #define WFULL(b)  (MB + (b) * 8)
    #define WEMPTY(b) (MB + 24 + (b) * 8)
    #define XFULL(b)  (MB + 48 + (b) * 8)
    #define XEMPTY(b) (MB + 64 + (b) * 8)

    if (tid == 0) {
        for (int b = 0; b < 3; ++b) { MBINIT(WFULL(b), 1); MBINIT(WEMPTY(b), 8); }
        for (int b = 0; b < 2; ++b) { MBINIT(XFULL(b), 1); MBINIT(XEMPTY(b), 8); }
    }
    float* psm = (float*)(smem + SM_PS);
    float* bsm = (float*)(smem + SM_BS);
    for (int j = tid; j < 128 * 16; j += 256) {
        int r = j >> 4, l = j & 15;
        psm[r * 17 + l] = g_probs[(size_t)(rt * 128 + r) * LL + grp * 16 + l];
    }
    for (int j = tid; j < 16 * CC; j += 256) bsm[j] = bias[grp * 16 * CC + j];
    __syncthreads();

    // prologue: W stages 0,1 ; X ks 0
    if (tid == 0) {
        #pragma unroll
        for (int s = 0; s < 2; ++s) {
            MBEXPECT(WFULL(s), WCH);
            BULK(sb + SM_W + s * WCH,
                 g_wb + (size_t)((grp * 16 + s) * 8 + 0) * WCH, WCH, WFULL(s));
        }
        MBEXPECT(XFULL(0), XCH);
        BULK(sb + SM_X, g_xb + (size_t)(rt * 8 + 0) * XCH, XCH, XFULL(0));
    }

    // per-thread invariant ldmatrix offsets (bytes within chunk)
    const uint32_t aoff0 = (uint32_t)(wm * 32 + ((lane >> 3) & 1) * 8 + (lane & 7)) * 144
                           + ((lane >> 4) & 1) * 16;
    const uint32_t aoff1 = aoff0 + 16 * 144;
    const uint32_t boff0 = (uint32_t)(wn * 40 + ((lane >> 4) & 1) * 8 + (lane & 7)) * 144
                           + ((lane >> 3) & 1) * 16;
    const uint32_t boff1 = boff0 + 16 * 144;
    const int l16 = lane & 15;
    const uint32_t boff2 = (uint32_t)(wn * 40 + 32 + (l16 & 7)) * 144 + ((l16 >> 3) & 1) * 16;

    float per[2][5][4] = {};
    uint32_t ah[4][2][4];   // A fragments for current ks: [kc][mtile][4]
    int cwf[3] = {0, 0, 0}, cxf[2] = {0, 0};
    int pwe[3] = {0, 0, 0}, pxe[2] = {0, 0};

    for (int s = 0; s < 128; ++s) {
        const int b = s % 3;
        const int ks = s >> 4, leaf = s & 15;
        const int xb = ks & 1;

        if (tid == 0) {
            int sn = s + 2;
            if (sn < 128) {
                int bn = sn % 3;
                if (sn >= 3) { mbwait(WEMPTY(bn), pwe[bn] & 1); pwe[bn]++; }
                MBEXPECT(WFULL(bn), WCH);
                int lf = grp * 16 + (sn & 15), kn = sn >> 4;
                BULK(sb + SM_W + bn * WCH,
                     g_wb + (size_t)(lf * 8 + kn) * WCH, WCH, WFULL(bn));
            }
            if (leaf == 4 && ks + 1 < 8) {
                int kn = ks + 1, xbn = kn & 1;
                if (kn >= 2) { mbwait(XEMPTY(xbn), pxe[xbn] & 1); pxe[xbn]++; }
                MBEXPECT(XFULL(xbn), XCH);
                BULK(sb + SM_X + xbn * XCH,
                     g_xb + (size_t)(rt * 8 + kn) * XCH, XCH, XFULL(xbn));
            }
        }

        mbwait(WFULL(b), cwf[b] & 1); cwf[b]++;

        if (leaf == 0) {
            // hoist A fragments for this ks into registers (reused for 16 leaves)
            mbwait(XFULL(xb), cxf[xb] & 1); cxf[xb]++;
            const uint32_t xh = sb + SM_X + xb * XCH;
            #pragma unroll
            for (int kc = 0; kc < 4; ++kc) {
                ldsm4(ah[kc][0], xh + aoff0 + kc * 32);
                ldsm4(ah[kc][1], xh + aoff1 + kc * 32);
            }
            if (lane == 0) MBARRIVE(XEMPTY(xb));   // regs hold A; smem X reusable
        }

        float acc[2][5][4];
        if (ks == 0) {
            #pragma unroll
            for (int nt = 0; nt < 5; ++nt) {
                int c0 = wn * 40 + nt * 8 + lc * 2;
                float b0 = bsm[leaf * CC + c0], b1 = bsm[leaf * CC + c0 + 1];
                #pragma unroll
                for (int mt = 0; mt < 2; ++mt) {
                    acc[mt][nt][0] = b0; acc[mt][nt][1] = b1;
                    acc[mt][nt][2] = b0; acc[mt][nt][3] = b1;
                }
            }
        } else {
            #pragma unroll
            for (int mt = 0; mt < 2; ++mt)
                #pragma unroll
                for (int nt = 0; nt < 5; ++nt)
                    acc[mt][nt][0] = acc[mt][nt][1] = acc[mt][nt][2] = acc[mt][nt][3] = 0.f;
        }

        const uint32_t wh = sb + SM_W + b * WCH;

        #pragma unroll
        for (int kc = 0; kc < 4; ++kc) {
            const int ko = kc * 32;
            uint32_t bh[5][2];
            ldsm4(&bh[0][0], wh + boff0 + ko);
            ldsm4(&bh[2][0], wh + boff1 + ko);
            ldsm2(&bh[4][0], wh + boff2 + ko);
            #pragma unroll
            for (int mt = 0; mt < 2; ++mt)
                #pragma unroll
                for (int nt = 0; nt < 5; ++nt)
                    mma_f16(acc[mt][nt], ah[kc][mt], bh[nt]);
        }

        // fold probability (linearity: out = sum over chunks of p * chunk)
        #pragma unroll
        for (int mt = 0; mt < 2; ++mt) {
            float p0 = psm[(wm * 32 + mt * 16 + lr) * 17 + leaf];
            float p1 = psm[(wm * 32 + mt * 16 + 8 + lr) * 17 + leaf];
            #pragma unroll
            for (int nt = 0; nt < 5; ++nt) {
                per[mt][nt][0] = fmaf(p0, acc[mt][nt][0], per[mt][nt][0]);
                per[mt][nt][1] = fmaf(p0, acc[mt][nt][1], per[mt][nt][1]);
                per[mt][nt][2] = fmaf(p1, acc[mt][nt][2], per[mt][nt][2]);
                per[mt][nt][3] = fmaf(p1, acc[mt][nt][3], per[mt][nt][3]);
            }
        }

        if (lane == 0) MBARRIVE(WEMPTY(b));
    }

    float* base = g_partial + (size_t)grp * BB * CC;
    #pragma unroll
    for (int mt = 0; mt < 2; ++mt) {
        int r0 = rt * 128 + wm * 32 + mt * 16 + lr;
        #pragma unroll
        for (int nt = 0; nt < 5; ++nt) {
            int c0 = wn * 40 + nt * 8 + lc * 2;
            *(float2*)(base + (size_t)r0 * CC + c0) = make_float2(per[mt][nt][0], per[mt][nt][1]);
            *(float2*)(base + (size_t)(r0 + 8) * CC + c0) = make_float2(per[mt][nt][2], per[mt][nt][3]);
        }
    }
}

// ---------------- K6: reduce partials ----------------
__global__ void k_reduce(float* __restrict__ out) {
    int idx = blockIdx.x * 256 + threadIdx.x;
    float s = 0.f;
    #pragma unroll
    for (int g = 0; g < NGRP; ++g)
        s += g_partial[(size_t)g * BB * CC + idx];
    out[idx] = s;
}

// ---------------- launch ----------------
extern "C" void kernel_launch(void* const* d_in, const int* in_sizes, int n_in,
                              void* d_out, int out_size) {
    const float* x    = (const float*)d_in[0];
    const float* ne   = (const float*)d_in[1];
    const float* W    = (const float*)d_in[2];
    const float* bias = (const float*)d_in[3];

    float* out1 = (float*)d_out;
    float* ns   = (float*)d_out + BB * CC;

    cudaFuncSetAttribute(k_main, cudaFuncAttributeMaxDynamicSharedMemorySize, SMEM_MAIN);

    k_norm<<<KK, 128>>>(ne);
    dim3 g2(BB / 64, 4);
    k_nodesim<<<g2, 256>>>(x, ns);
    k_probs<<<BB, 256>>>(ns);
    k_convW<<<5120, 256>>>(W);
    k_convX<<<256, 256>>>(x);
    dim3 g5(8, NGRP);
    k_main<<<g5, 256, SMEM_MAIN>>>(bias);
    k_reduce<<<(BB * CC) / 256, 256>>>(out1);
}

// round 8
// speedup vs baseline: 5.2798x; 1.3757x over previous
#include <cuda_runtime.h>
#include <cuda_fp16.h>
#include <math.h>
#include <stdint.h>

#define BB 1024
#define DD 512
#define KK 255
#define LL 256
#define CC 80
#define NGRP 16

#define WCH 11520      // W chunk: 80 rows x 144B (fp16)
#define XCH 18432      // X chunk: 128 rows x 144B (fp16)

// ---- smem layout (bytes) ----
#define SM_X   0                     // 8 chunks x 18432 = 147456 (X resident)
#define SM_W   147456                // 4 bufs x 11520 = 46080
#define SM_PS  193536                // 128*17*4 = 8704
#define SM_BS  202240                // 16*80*4 = 5120
#define SM_MB  207360                // mbarriers (128B)
#define SMEM_MAIN 207488

// ---------------- device scratch ----------------
__device__ float g_ne[KK * DD];
__device__ float g_probs[BB * LL];
__device__ float g_partial[NGRP * BB * CC];
__device__ __align__(16) uint8_t g_wb[(size_t)LL * 8 * WCH];   // [leaf][ks][80x144B] fp16
__device__ __align__(16) uint8_t g_xb[(size_t)8 * 8 * XCH];    // [rt][ks][128x144B] fp16

// ---------------- helpers ----------------
__device__ __forceinline__ uint32_t s2u(const void* p) {
    uint32_t a;
    asm("{ .reg .u64 t; cvta.to.shared.u64 t, %1; cvt.u32.u64 %0, t; }" : "=r"(a) : "l"(p));
    return a;
}
#define MBINIT(m, c)  asm volatile("mbarrier.init.shared.b64 [%0], %1;" :: "r"(m), "r"(c) : "memory")
#define MBEXPECT(m, b) asm volatile("mbarrier.arrive.expect_tx.shared.b64 _, [%0], %1;" :: "r"(m), "r"(b) : "memory")
#define MBARRIVE(m)   asm volatile("mbarrier.arrive.shared.b64 _, [%0];" :: "r"(m) : "memory")
__device__ __forceinline__ void mbwait(uint32_t m, uint32_t ph) {
    asm volatile(
        "{\n .reg .pred P;\n"
        "LW_%=:\n mbarrier.try_wait.parity.acquire.cta.shared::cta.b64 P, [%0], %1, 0x989680;\n"
        " @P bra LD_%=;\n bra LW_%=;\nLD_%=:\n}"
        :: "r"(m), "r"(ph) : "memory");
}
#define BULK(dst, src, sz, mb) \
    asm volatile("cp.async.bulk.shared::cta.global.mbarrier::complete_tx::bytes [%0], [%1], %2, [%3];" \
                 :: "r"(dst), "l"(src), "r"(sz), "r"(mb) : "memory")

__device__ __forceinline__ void ldsm4(uint32_t* r, uint32_t a) {
    asm volatile("ldmatrix.sync.aligned.m8n8.x4.shared.b16 {%0,%1,%2,%3}, [%4];"
        : "=r"(r[0]), "=r"(r[1]), "=r"(r[2]), "=r"(r[3]) : "r"(a));
}
__device__ __forceinline__ void ldsm2(uint32_t* r, uint32_t a) {
    asm volatile("ldmatrix.sync.aligned.m8n8.x2.shared.b16 {%0,%1}, [%2];"
        : "=r"(r[0]), "=r"(r[1]) : "r"(a));
}
__device__ __forceinline__ void mma_f16(float* c, const uint32_t* a, const uint32_t* b) {
    asm volatile(
        "mma.sync.aligned.m16n8k16.row.col.f32.f16.f16.f32 "
        "{%0,%1,%2,%3}, {%4,%5,%6,%7}, {%8,%9}, {%0,%1,%2,%3};"
        : "+f"(c[0]), "+f"(c[1]), "+f"(c[2]), "+f"(c[3])
        : "r"(a[0]), "r"(a[1]), "r"(a[2]), "r"(a[3]), "r"(b[0]), "r"(b[1]));
}

// ---------------- K1: normalize node embeddings ----------------
__global__ void k_norm(const float* __restrict__ ne) {
    int k = blockIdx.x;
    int t = threadIdx.x;
    const float* row = ne + (size_t)k * DD;
    float s = 0.f;
    for (int d = t; d < DD; d += 128) { float v = row[d]; s += v * v; }
    __shared__ float red[4];
    #pragma unroll
    for (int o = 16; o > 0; o >>= 1) s += __shfl_xor_sync(0xffffffffu, s, o);
    if ((t & 31) == 0) red[t >> 5] = s;
    __syncthreads();
    float inv = 1.0f / sqrtf(red[0] + red[1] + red[2] + red[3]);
    for (int d = t; d < DD; d += 128) g_ne[(size_t)k * DD + d] = row[d] * inv;
}

// ---------------- K2: node_sim = sigmoid(x @ ne^T) ----------------
__global__ void k_nodesim(const float* __restrict__ x, float* __restrict__ out_ns) {
    __shared__ float xt[64 * 32];
    __shared__ float nt[64 * 36];
    int row0 = blockIdx.x * 64;
    int col0 = blockIdx.y * 64;
    int tid = threadIdx.x;
    int tx = tid & 15, ty = tid >> 4;
    float acc[4][4] = {};
    for (int dk = 0; dk < 16; ++dk) {
        #pragma unroll
        for (int i = 0; i < 2; ++i) {
            int idx = tid + i * 256;
            int r = idx >> 3, dg = idx & 7;
            float4 v = *(const float4*)(x + (size_t)(row0 + r) * DD + dk * 32 + dg * 4);
            *(float4*)(xt + r * 32 + dg * 4) = v;
        }
        #pragma unroll
        for (int i = 0; i < 2; ++i) {
            int idx = tid + i * 256;
            int r = idx >> 3, dg = idx & 7;
            int kk = col0 + r;
            float4 v = make_float4(0.f, 0.f, 0.f, 0.f);
            if (kk < KK) v = *(const float4*)(g_ne + (size_t)kk * DD + dk * 32 + dg * 4);
            *(float4*)(nt + r * 36 + dg * 4) = v;
        }
        __syncthreads();
        #pragma unroll
        for (int k = 0; k < 32; ++k) {
            float xf[4], nf[4];
            #pragma unroll
            for (int i = 0; i < 4; ++i) xf[i] = xt[(ty * 4 + i) * 32 + k];
            #pragma unroll
            for (int j = 0; j < 4; ++j) nf[j] = nt[(tx + 16 * j) * 36 + k];
            #pragma unroll
            for (int i = 0; i < 4; ++i)
                #pragma unroll
                for (int j = 0; j < 4; ++j) acc[i][j] += xf[i] * nf[j];
        }
        __syncthreads();
    }
    #pragma unroll
    for (int i = 0; i < 4; ++i)
        #pragma unroll
        for (int j = 0; j < 4; ++j) {
            int r = row0 + ty * 4 + i, c = col0 + tx + 16 * j;
            if (c < KK) out_ns[(size_t)r * KK + c] = 1.0f / (1.0f + expf(-acc[i][j]));
        }
}

// ---------------- K3: leaf probabilities ----------------
__global__ void k_probs(const float* __restrict__ ns) {
    int b = blockIdx.x;
    int leaf = threadIdx.x;
    __shared__ float s[KK];
    if (leaf < KK) s[leaf] = ns[(size_t)b * KK + leaf];
    __syncthreads();
    float p = 1.0f; int node = 0;
    #pragma unroll
    for (int d = 0; d < 8; ++d) {
        int bit = (leaf >> (7 - d)) & 1;
        float v = s[node];
        p *= bit ? (1.0f - v) : v;
        node = 2 * node + 1 + bit;
    }
    g_probs[(size_t)b * LL + leaf] = p;
}

// ---------------- conversion kernels ----------------
__global__ void k_convW(const float* __restrict__ W) {
    int t = blockIdx.x * 256 + threadIdx.x;      // 20480*64
    int row = t >> 6;
    int kg = t & 63;
    int leaf = row / 80, n = row - leaf * 80;
    int ks = kg >> 3, k8 = kg & 7;
    float4 a = *(const float4*)(W + (size_t)row * 512 + kg * 8);
    float4 b = *(const float4*)(W + (size_t)row * 512 + kg * 8 + 4);
    float v[8] = {a.x, a.y, a.z, a.w, b.x, b.y, b.z, b.w};
    unsigned short hb[8];
    #pragma unroll
    for (int i = 0; i < 8; ++i) hb[i] = __half_as_ushort(__float2half_rn(v[i]));
    uint4 HI = make_uint4(((uint32_t)hb[1] << 16) | hb[0], ((uint32_t)hb[3] << 16) | hb[2],
                          ((uint32_t)hb[5] << 16) | hb[4], ((uint32_t)hb[7] << 16) | hb[6]);
    *(uint4*)(g_wb + (size_t)(leaf * 8 + ks) * WCH + n * 144 + k8 * 16) = HI;
}
__global__ void k_convX(const float* __restrict__ x) {
    int t = blockIdx.x * 256 + threadIdx.x;      // 1024*64
    int row = t >> 6;
    int kg = t & 63;
    int rt = row >> 7, r = row & 127;
    int ks = kg >> 3, k8 = kg & 7;
    float4 a = *(const float4*)(x + (size_t)row * 512 + kg * 8);
    float4 b = *(const float4*)(x + (size_t)row * 512 + kg * 8 + 4);
    float v[8] = {a.x, a.y, a.z, a.w, b.x, b.y, b.z, b.w};
    unsigned short hb[8];
    #pragma unroll
    for (int i = 0; i < 8; ++i) hb[i] = __half_as_ushort(__float2half_rn(v[i]));
    *(uint4*)(g_xb + (size_t)(rt * 8 + ks) * XCH + r * 144 + k8 * 16) =
        make_uint4(((uint32_t)hb[1] << 16) | hb[0], ((uint32_t)hb[3] << 16) | hb[2],
                   ((uint32_t)hb[5] << 16) | hb[4], ((uint32_t)hb[7] << 16) | hb[6]);
}

// ---------------- K5: main HMMA kernel (leaf-outer, X resident) ----------------
// grid (8 rowtiles, 16 leaf-groups), 256 threads = 8 warps (4 M x 2 N).
// leaf outer (0..15), ks inner (0..7); acc persists over ks; fold once per leaf.
__global__ void __launch_bounds__(256, 1) k_main(const float* __restrict__ bias) {
    extern __shared__ char smem[];
    const uint32_t sb = s2u(smem);
    const int tid = threadIdx.x;
    const int rt = blockIdx.x, grp = blockIdx.y;
    const int wid = tid >> 5, lane = tid & 31;
    const int wm = wid >> 1, wn = wid & 1;
    const int lr = lane >> 2, lc = lane & 3;

    const uint32_t MB = sb + SM_MB;
    #define WFULL(b)  (MB + (b) * 8)
    #define WEMPTY(b) (MB + 32 + (b) * 8)
    #define XFULL     (MB + 64)

    if (tid == 0) {
        for (int b = 0; b < 4; ++b) { MBINIT(WFULL(b), 1); MBINIT(WEMPTY(b), 8); }
        MBINIT(XFULL, 1);
    }
    float* psm = (float*)(smem + SM_PS);
    float* bsm = (float*)(smem + SM_BS);
    for (int j = tid; j < 128 * 16; j += 256) {
        int r = j >> 4, l = j & 15;
        psm[r * 17 + l] = g_probs[(size_t)(rt * 128 + r) * LL + grp * 16 + l];
    }
    for (int j = tid; j < 16 * CC; j += 256) bsm[j] = bias[grp * 16 * CC + j];
    __syncthreads();

    // prologue: all X chunks + W stages 0..2
    if (tid == 0) {
        MBEXPECT(XFULL, 8 * XCH);
        #pragma unroll
        for (int j = 0; j < 8; ++j)
            BULK(sb + SM_X + j * XCH, g_xb + (size_t)(rt * 8 + j) * XCH, XCH, XFULL);
        #pragma unroll
        for (int s = 0; s < 3; ++s) {
            MBEXPECT(WFULL(s), WCH);
            BULK(sb + SM_W + s * WCH,
                 g_wb + (size_t)(grp * 16 * 8 + s) * WCH, WCH, WFULL(s));
        }
    }

    // per-thread invariant ldmatrix offsets (bytes within chunk)
    const uint32_t aoff0 = (uint32_t)(wm * 32 + ((lane >> 3) & 1) * 8 + (lane & 7)) * 144
                           + ((lane >> 4) & 1) * 16;
    const uint32_t aoff1 = aoff0 + 16 * 144;
    const uint32_t boff0 = (uint32_t)(wn * 40 + ((lane >> 4) & 1) * 8 + (lane & 7)) * 144
                           + ((lane >> 3) & 1) * 16;
    const uint32_t boff1 = boff0 + 16 * 144;
    const int l16 = lane & 15;
    const uint32_t boff2 = (uint32_t)(wn * 40 + 32 + (l16 & 7)) * 144 + ((l16 >> 3) & 1) * 16;

    float per[2][5][4] = {};
    int cwf[4] = {0, 0, 0, 0}, pwe[4] = {0, 0, 0, 0};

    mbwait(XFULL, 0);   // X resident from here on

    for (int leaf = 0; leaf < 16; ++leaf) {
        // acc init with bias (folded once per leaf)
        float acc[2][5][4];
        #pragma unroll
        for (int nt = 0; nt < 5; ++nt) {
            int c0 = wn * 40 + nt * 8 + lc * 2;
            float b0 = bsm[leaf * CC + c0], b1 = bsm[leaf * CC + c0 + 1];
            #pragma unroll
            for (int mt = 0; mt < 2; ++mt) {
                acc[mt][nt][0] = b0; acc[mt][nt][1] = b1;
                acc[mt][nt][2] = b0; acc[mt][nt][3] = b1;
            }
        }

        for (int ks = 0; ks < 8; ++ks) {
            const int s = leaf * 8 + ks, b = s & 3;

            if (tid == 0) {
                int sn = s + 3;
                if (sn < 128) {
                    int bn = sn & 3;
                    if (sn >= 4) { mbwait(WEMPTY(bn), pwe[bn] & 1); pwe[bn]++; }
                    MBEXPECT(WFULL(bn), WCH);
                    BULK(sb + SM_W + bn * WCH,
                         g_wb + (size_t)(grp * 16 * 8 + sn) * WCH, WCH, WFULL(bn));
                }
            }

            mbwait(WFULL(b), cwf[b] & 1); cwf[b]++;
            const uint32_t xk = sb + SM_X + ks * XCH;
            const uint32_t wh = sb + SM_W + b * WCH;

            #pragma unroll
            for (int kc = 0; kc < 4; ++kc) {
                const int ko = kc * 32;
                uint32_t ah[2][4], bh[5][2];
                ldsm4(ah[0], xk + aoff0 + ko);
                ldsm4(ah[1], xk + aoff1 + ko);
                ldsm4(&bh[0][0], wh + boff0 + ko);
                ldsm4(&bh[2][0], wh + boff1 + ko);
                ldsm2(&bh[4][0], wh + boff2 + ko);
                #pragma unroll
                for (int mt = 0; mt < 2; ++mt)
                    #pragma unroll
                    for (int nt = 0; nt < 5; ++nt)
                        mma_f16(acc[mt][nt], ah[mt], bh[nt]);
            }

            if (lane == 0) MBARRIVE(WEMPTY(b));
        }

        // fold probability once per leaf
        #pragma unroll
        for (int mt = 0; mt < 2; ++mt) {
            float p0 = psm[(wm * 32 + mt * 16 + lr) * 17 + leaf];
            float p1 = psm[(wm * 32 + mt * 16 + 8 + lr) * 17 + leaf];
            #pragma unroll
            for (int nt = 0; nt < 5; ++nt) {
                per[mt][nt][0] = fmaf(p0, acc[mt][nt][0], per[mt][nt][0]);
                per[mt][nt][1] = fmaf(p0, acc[mt][nt][1], per[mt][nt][1]);
                per[mt][nt][2] = fmaf(p1, acc[mt][nt][2], per[mt][nt][2]);
                per[mt][nt][3] = fmaf(p1, acc[mt][nt][3], per[mt][nt][3]);
            }
        }
    }

    float* base = g_partial + (size_t)grp * BB * CC;
    #pragma unroll
    for (int mt = 0; mt < 2; ++mt) {
        int r0 = rt * 128 + wm * 32 + mt * 16 + lr;
        #pragma unroll
        for (int nt = 0; nt < 5; ++nt) {
            int c0 = wn * 40 + nt * 8 + lc * 2;
            *(float2*)(base + (size_t)r0 * CC + c0) = make_float2(per[mt][nt][0], per[mt][nt][1]);
            *(float2*)(base + (size_t)(r0 + 8) * CC + c0) = make_float2(per[mt][nt][2], per[mt][nt][3]);
        }
    }
}

// ---------------- K6: reduce partials ----------------
__global__ void k_reduce(float* __restrict__ out) {
    int idx = blockIdx.x * 256 + threadIdx.x;
    float s = 0.f;
    #pragma unroll
    for (int g = 0; g < NGRP; ++g)
        s += g_partial[(size_t)g * BB * CC + idx];
    out[idx] = s;
}

// ---------------- launch ----------------
extern "C" void kernel_launch(void* const* d_in, const int* in_sizes, int n_in,
                              void* d_out, int out_size) {
    const float* x    = (const float*)d_in[0];
    const float* ne   = (const float*)d_in[1];
    const float* W    = (const float*)d_in[2];
    const float* bias = (const float*)d_in[3];

    float* out1 = (float*)d_out;
    float* ns   = (float*)d_out + BB * CC;

    cudaFuncSetAttribute(k_main, cudaFuncAttributeMaxDynamicSharedMemorySize, SMEM_MAIN);

    k_norm<<<KK, 128>>>(ne);
    dim3 g2(BB / 64, 4);
    k_nodesim<<<g2, 256>>>(x, ns);
    k_probs<<<BB, 256>>>(ns);
    k_convW<<<5120, 256>>>(W);
    k_convX<<<256, 256>>>(x);
    dim3 g5(8, NGRP);
    k_main<<<g5, 256, SMEM_MAIN>>>(bias);
    k_reduce<<<(BB * CC) / 256, 256>>>(out1);
}

// round 9
// speedup vs baseline: 5.3724x; 1.0175x over previous
#include <cuda_runtime.h>
#include <cuda_fp16.h>
#include <math.h>
#include <stdint.h>

#define BB 1024
#define DD 512
#define KK 255
#define LL 256
#define CC 80
#define NGRP 16

#define WCH 11520      // W chunk: 80 rows x 144B (fp16)
#define XCH 18432      // X chunk: 128 rows x 144B (fp16)

// ---- smem layout (bytes) ----
#define SM_X   0                     // 8 chunks x 18432 = 147456 (X resident)
#define SM_W   147456                // 4 bufs x 11520 = 46080
#define SM_PS  193536                // 128*17*4 = 8704
#define SM_BS  202240                // 16*80*4 = 5120
#define SM_MB  207360                // mbarriers (128B)
#define SMEM_MAIN 207488

// ---------------- device scratch ----------------
__device__ float g_ne[KK * DD];
__device__ float g_probs[BB * LL];
__device__ float g_partial[NGRP * BB * CC];
__device__ __align__(16) uint8_t g_wb[(size_t)LL * 8 * WCH];   // [leaf][ks][80x144B] fp16
__device__ __align__(16) uint8_t g_xb[(size_t)8 * 8 * XCH];    // [rt][ks][128x144B] fp16

// ---------------- helpers ----------------
__device__ __forceinline__ uint32_t s2u(const void* p) {
    uint32_t a;
    asm("{ .reg .u64 t; cvta.to.shared.u64 t, %1; cvt.u32.u64 %0, t; }" : "=r"(a) : "l"(p));
    return a;
}
#define MBINIT(m, c)  asm volatile("mbarrier.init.shared.b64 [%0], %1;" :: "r"(m), "r"(c) : "memory")
#define MBEXPECT(m, b) asm volatile("mbarrier.arrive.expect_tx.shared.b64 _, [%0], %1;" :: "r"(m), "r"(b) : "memory")
#define MBARRIVE(m)   asm volatile("mbarrier.arrive.shared.b64 _, [%0];" :: "r"(m) : "memory")
__device__ __forceinline__ void mbwait(uint32_t m, uint32_t ph) {
    asm volatile(
        "{\n .reg .pred P;\n"
        "LW_%=:\n mbarrier.try_wait.parity.acquire.cta.shared::cta.b64 P, [%0], %1, 0x989680;\n"
        " @P bra LD_%=;\n bra LW_%=;\nLD_%=:\n}"
        :: "r"(m), "r"(ph) : "memory");
}
#define BULK(dst, src, sz, mb) \
    asm volatile("cp.async.bulk.shared::cta.global.mbarrier::complete_tx::bytes [%0], [%1], %2, [%3];" \
                 :: "r"(dst), "l"(src), "r"(sz), "r"(mb) : "memory")

__device__ __forceinline__ void ldsm4(uint32_t* r, uint32_t a) {
    asm volatile("ldmatrix.sync.aligned.m8n8.x4.shared.b16 {%0,%1,%2,%3}, [%4];"
        : "=r"(r[0]), "=r"(r[1]), "=r"(r[2]), "=r"(r[3]) : "r"(a));
}
__device__ __forceinline__ void ldsm2(uint32_t* r, uint32_t a) {
    asm volatile("ldmatrix.sync.aligned.m8n8.x2.shared.b16 {%0,%1}, [%2];"
        : "=r"(r[0]), "=r"(r[1]) : "r"(a));
}
__device__ __forceinline__ void mma_f16(float* c, const uint32_t* a, const uint32_t* b) {
    asm volatile(
        "mma.sync.aligned.m16n8k16.row.col.f32.f16.f16.f32 "
        "{%0,%1,%2,%3}, {%4,%5,%6,%7}, {%8,%9}, {%0,%1,%2,%3};"
        : "+f"(c[0]), "+f"(c[1]), "+f"(c[2]), "+f"(c[3])
        : "r"(a[0]), "r"(a[1]), "r"(a[2]), "r"(a[3]), "r"(b[0]), "r"(b[1]));
}

// ---------------- K1: normalize node embeddings ----------------
__global__ void k_norm(const float* __restrict__ ne) {
    int k = blockIdx.x;
    int t = threadIdx.x;
    const float* row = ne + (size_t)k * DD;
    float s = 0.f;
    for (int d = t; d < DD; d += 128) { float v = row[d]; s += v * v; }
    __shared__ float red[4];
    #pragma unroll
    for (int o = 16; o > 0; o >>= 1) s += __shfl_xor_sync(0xffffffffu, s, o);
    if ((t & 31) == 0) red[t >> 5] = s;
    __syncthreads();
    float inv = 1.0f / sqrtf(red[0] + red[1] + red[2] + red[3]);
    for (int d = t; d < DD; d += 128) g_ne[(size_t)k * DD + d] = row[d] * inv;
}

// ---------------- K2: node_sim = sigmoid(x @ ne^T) ----------------
__global__ void k_nodesim(const float* __restrict__ x, float* __restrict__ out_ns) {
    __shared__ float xt[64 * 32];
    __shared__ float nt[64 * 36];
    int row0 = blockIdx.x * 64;
    int col0 = blockIdx.y * 64;
    int tid = threadIdx.x;
    int tx = tid & 15, ty = tid >> 4;
    float acc[4][4] = {};
    for (int dk = 0; dk < 16; ++dk) {
        #pragma unroll
        for (int i = 0; i < 2; ++i) {
            int idx = tid + i * 256;
            int r = idx >> 3, dg = idx & 7;
            float4 v = *(const float4*)(x + (size_t)(row0 + r) * DD + dk * 32 + dg * 4);
            *(float4*)(xt + r * 32 + dg * 4) = v;
        }
        #pragma unroll
        for (int i = 0; i < 2; ++i) {
            int idx = tid + i * 256;
            int r = idx >> 3, dg = idx & 7;
            int kk = col0 + r;
            float4 v = make_float4(0.f, 0.f, 0.f, 0.f);
            if (kk < KK) v = *(const float4*)(g_ne + (size_t)kk * DD + dk * 32 + dg * 4);
            *(float4*)(nt + r * 36 + dg * 4) = v;
        }
        __syncthreads();
        #pragma unroll
        for (int k = 0; k < 32; ++k) {
            float xf[4], nf[4];
            #pragma unroll
            for (int i = 0; i < 4; ++i) xf[i] = xt[(ty * 4 + i) * 32 + k];
            #pragma unroll
            for (int j = 0; j < 4; ++j) nf[j] = nt[(tx + 16 * j) * 36 + k];
            #pragma unroll
            for (int i = 0; i < 4; ++i)
                #pragma unroll
                for (int j = 0; j < 4; ++j) acc[i][j] += xf[i] * nf[j];
        }
        __syncthreads();
    }
    #pragma unroll
    for (int i = 0; i < 4; ++i)
        #pragma unroll
        for (int j = 0; j < 4; ++j) {
            int r = row0 + ty * 4 + i, c = col0 + tx + 16 * j;
            if (c < KK) out_ns[(size_t)r * KK + c] = 1.0f / (1.0f + expf(-acc[i][j]));
        }
}

// ---------------- K3: leaf probabilities ----------------
__global__ void k_probs(const float* __restrict__ ns) {
    int b = blockIdx.x;
    int leaf = threadIdx.x;
    __shared__ float s[KK];
    if (leaf < KK) s[leaf] = ns[(size_t)b * KK + leaf];
    __syncthreads();
    float p = 1.0f; int node = 0;
    #pragma unroll
    for (int d = 0; d < 8; ++d) {
        int bit = (leaf >> (7 - d)) & 1;
        float v = s[node];
        p *= bit ? (1.0f - v) : v;
        node = 2 * node + 1 + bit;
    }
    g_probs[(size_t)b * LL + leaf] = p;
}

// ---------------- conversion kernels ----------------
__global__ void k_convW(const float* __restrict__ W) {
    int t = blockIdx.x * 256 + threadIdx.x;      // 20480*64
    int row = t >> 6;
    int kg = t & 63;
    int leaf = row / 80, n = row - leaf * 80;
    int ks = kg >> 3, k8 = kg & 7;
    float4 a = *(const float4*)(W + (size_t)row * 512 + kg * 8);
    float4 b = *(const float4*)(W + (size_t)row * 512 + kg * 8 + 4);
    float v[8] = {a.x, a.y, a.z, a.w, b.x, b.y, b.z, b.w};
    unsigned short hb[8];
    #pragma unroll
    for (int i = 0; i < 8; ++i) hb[i] = __half_as_ushort(__float2half_rn(v[i]));
    uint4 HI = make_uint4(((uint32_t)hb[1] << 16) | hb[0], ((uint32_t)hb[3] << 16) | hb[2],
                          ((uint32_t)hb[5] << 16) | hb[4], ((uint32_t)hb[7] << 16) | hb[6]);
    *(uint4*)(g_wb + (size_t)(leaf * 8 + ks) * WCH + n * 144 + k8 * 16) = HI;
}
__global__ void k_convX(const float* __restrict__ x) {
    int t = blockIdx.x * 256 + threadIdx.x;      // 1024*64
    int row = t >> 6;
    int kg = t & 63;
    int rt = row >> 7, r = row & 127;
    int ks = kg >> 3, k8 = kg & 7;
    float4 a = *(const float4*)(x + (size_t)row * 512 + kg * 8);
    float4 b = *(const float4*)(x + (size_t)row * 512 + kg * 8 + 4);
    float v[8] = {a.x, a.y, a.z, a.w, b.x, b.y, b.z, b.w};
    unsigned short hb[8];
    #pragma unroll
    for (int i = 0; i < 8; ++i) hb[i] = __half_as_ushort(__float2half_rn(v[i]));
    *(uint4*)(g_xb + (size_t)(rt * 8 + ks) * XCH + r * 144 + k8 * 16) =
        make_uint4(((uint32_t)hb[1] << 16) | hb[0], ((uint32_t)hb[3] << 16) | hb[2],
                   ((uint32_t)hb[5] << 16) | hb[4], ((uint32_t)hb[7] << 16) | hb[6]);
}

// ---------------- K5: main HMMA kernel (leaf-outer, X resident) ----------------
// grid (8 rowtiles, 16 leaf-groups), 256 threads = 8 warps (4 M x 2 N).
// leaf outer (0..15), ks inner (0..7); acc persists over ks; fold once per leaf.
__global__ void __launch_bounds__(256, 1) k_main(const float* __restrict__ bias) {
    extern __shared__ char smem[];
    const uint32_t sb = s2u(smem);
    const int tid = threadIdx.x;
    const int rt = blockIdx.x, grp = blockIdx.y;
    const int wid = tid >> 5, lane = tid & 31;
    const int wm = wid >> 1, wn = wid & 1;
    const int lr = lane >> 2, lc = lane & 3;

    const uint32_t MB = sb + SM_MB;
    #define WFULL(b)  (MB + (b) * 8)
    #define WEMPTY(b) (MB + 32 + (b) * 8)
    #define XFULL     (MB + 64)

    if (tid == 0) {
        for (int b = 0; b < 4; ++b) { MBINIT(WFULL(b), 1); MBINIT(WEMPTY(b), 8); }
        MBINIT(XFULL, 1);
    }
    float* psm = (float*)(smem + SM_PS);
    float* bsm = (float*)(smem + SM_BS);
    for (int j = tid; j < 128 * 16; j += 256) {
        int r = j >> 4, l = j & 15;
        psm[r * 17 + l] = g_probs[(size_t)(rt * 128 + r) * LL + grp * 16 + l];
    }
    for (int j = tid; j < 16 * CC; j += 256) bsm[j] = bias[grp * 16 * CC + j];
    __syncthreads();

    // prologue: all X chunks + W stages 0..2
    if (tid == 0) {
        MBEXPECT(XFULL, 8 * XCH);
        #pragma unroll
        for (int j = 0; j < 8; ++j)
            BULK(sb + SM_X + j * XCH, g_xb + (size_t)(rt * 8 + j) * XCH, XCH, XFULL);
        #pragma unroll
        for (int s = 0; s < 3; ++s) {
            MBEXPECT(WFULL(s), WCH);
            BULK(sb + SM_W + s * WCH,
                 g_wb + (size_t)(grp * 16 * 8 + s) * WCH, WCH, WFULL(s));
        }
    }

    // per-thread invariant ldmatrix offsets (bytes within chunk)
    const uint32_t aoff0 = (uint32_t)(wm * 32 + ((lane >> 3) & 1) * 8 + (lane & 7)) * 144
                           + ((lane >> 4) & 1) * 16;
    const uint32_t aoff1 = aoff0 + 16 * 144;
    const uint32_t boff0 = (uint32_t)(wn * 40 + ((lane >> 4) & 1) * 8 + (lane & 7)) * 144
                           + ((lane >> 3) & 1) * 16;
    const uint32_t boff1 = boff0 + 16 * 144;
    const int l16 = lane & 15;
    const uint32_t boff2 = (uint32_t)(wn * 40 + 32 + (l16 & 7)) * 144 + ((l16 >> 3) & 1) * 16;

    float per[2][5][4] = {};
    int cwf[4] = {0, 0, 0, 0}, pwe[4] = {0, 0, 0, 0};

    mbwait(XFULL, 0);   // X resident from here on

    for (int leaf = 0; leaf < 16; ++leaf) {
        // acc init with bias (folded once per leaf)
        float acc[2][5][4];
        #pragma unroll
        for (int nt = 0; nt < 5; ++nt) {
            int c0 = wn * 40 + nt * 8 + lc * 2;
            float b0 = bsm[leaf * CC + c0], b1 = bsm[leaf * CC + c0 + 1];
            #pragma unroll
            for (int mt = 0; mt < 2; ++mt) {
                acc[mt][nt][0] = b0; acc[mt][nt][1] = b1;
                acc[mt][nt][2] = b0; acc[mt][nt][3] = b1;
            }
        }

        for (int ks = 0; ks < 8; ++ks) {
            const int s = leaf * 8 + ks, b = s & 3;

            if (tid == 0) {
                int sn = s + 3;
                if (sn < 128) {
                    int bn = sn & 3;
                    if (sn >= 4) { mbwait(WEMPTY(bn), pwe[bn] & 1); pwe[bn]++; }
                    MBEXPECT(WFULL(bn), WCH);
                    BULK(sb + SM_W + bn * WCH,
                         g_wb + (size_t)(grp * 16 * 8 + sn) * WCH, WCH, WFULL(bn));
                }
            }

            mbwait(WFULL(b), cwf[b] & 1); cwf[b]++;
            const uint32_t xk = sb + SM_X + ks * XCH;
            const uint32_t wh = sb + SM_W + b * WCH;

            #pragma unroll
            for (int kc = 0; kc < 4; ++kc) {
                const int ko = kc * 32;
                uint32_t ah[2][4], bh[5][2];
                ldsm4(ah[0], xk + aoff0 + ko);
                ldsm4(ah[1], xk + aoff1 + ko);
                ldsm4(&bh[0][0], wh + boff0 + ko);
                ldsm4(&bh[2][0], wh + boff1 + ko);
                ldsm2(&bh[4][0], wh + boff2 + ko);
                #pragma unroll
                for (int mt = 0; mt < 2; ++mt)
                    #pragma unroll
                    for (int nt = 0; nt < 5; ++nt)
                        mma_f16(acc[mt][nt], ah[mt], bh[nt]);
            }

            if (lane == 0) MBARRIVE(WEMPTY(b));
        }

        // fold probability once per leaf
        #pragma unroll
        for (int mt = 0; mt < 2; ++mt) {
            float p0 = psm[(wm * 32 + mt * 16 + lr) * 17 + leaf];
            float p1 = psm[(wm * 32 + mt * 16 + 8 + lr) * 17 + leaf];
            #pragma unroll
            for (int nt = 0; nt < 5; ++nt) {
                per[mt][nt][0] = fmaf(p0, acc[mt][nt][0], per[mt][nt][0]);
                per[mt][nt][1] = fmaf(p0, acc[mt][nt][1], per[mt][nt][1]);
                per[mt][nt][2] = fmaf(p1, acc[mt][nt][2], per[mt][nt][2]);
                per[mt][nt][3] = fmaf(p1, acc[mt][nt][3], per[mt][nt][3]);
            }
        }
    }

    float* base = g_partial + (size_t)grp * BB * CC;
    #pragma unroll
    for (int mt = 0; mt < 2; ++mt) {
        int r0 = rt * 128 + wm * 32 + mt * 16 + lr;
        #pragma unroll
        for (int nt = 0; nt < 5; ++nt) {
            int c0 = wn * 40 + nt * 8 + lc * 2;
            *(float2*)(base + (size_t)r0 * CC + c0) = make_float2(per[mt][nt][0], per[mt][nt][1]);
            *(float2*)(base + (size_t)(r0 + 8) * CC + c0) = make_float2(per[mt][nt][2], per[mt][nt][3]);
        }
    }
}

// ---------------- K6: reduce partials ----------------
__global__ void k_reduce(float* __restrict__ out) {
    int idx = blockIdx.x * 256 + threadIdx.x;
    float s = 0.f;
    #pragma unroll
    for (int g = 0; g < NGRP; ++g)
        s += g_partial[(size_t)g * BB * CC + idx];
    out[idx] = s;
}

// ---------------- launch (fork/join multi-stream for graph parallelism) ----------------
extern "C" void kernel_launch(void* const* d_in, const int* in_sizes, int n_in,
                              void* d_out, int out_size) {
    const float* x    = (const float*)d_in[0];
    const float* ne   = (const float*)d_in[1];
    const float* W    = (const float*)d_in[2];
    const float* bias = (const float*)d_in[3];

    float* out1 = (float*)d_out;
    float* ns   = (float*)d_out + BB * CC;

    cudaFuncSetAttribute(k_main, cudaFuncAttributeMaxDynamicSharedMemorySize, SMEM_MAIN);

    // side stream for the conversion branch (independent of norm/nodesim/probs)
    cudaStream_t s2;
    cudaEvent_t eFork, eJoin;
    cudaStreamCreateWithFlags(&s2, cudaStreamNonBlocking);
    cudaEventCreateWithFlags(&eFork, cudaEventDisableTiming);
    cudaEventCreateWithFlags(&eJoin, cudaEventDisableTiming);

    cudaEventRecord(eFork, 0);
    cudaStreamWaitEvent(s2, eFork, 0);

    // branch A (side stream): conversions
    k_convW<<<5120, 256, 0, s2>>>(W);
    k_convX<<<256, 256, 0, s2>>>(x);
    cudaEventRecord(eJoin, s2);

    // branch B (main stream): node-sim chain
    k_norm<<<KK, 128>>>(ne);
    dim3 g2(BB / 64, 4);
    k_nodesim<<<g2, 256>>>(x, ns);
    k_probs<<<BB, 256>>>(ns);

    // join, then main GEMM + reduce
    cudaStreamWaitEvent(0, eJoin, 0);
    dim3 g5(8, NGRP);
    k_main<<<g5, 256, SMEM_MAIN>>>(bias);
    k_reduce<<<(BB * CC) / 256, 256>>>(out1);

    // note: s2/eFork/eJoin intentionally not destroyed here — destroying
    // capture-referenced handles mid-capture is UB; kernel_launch is called
    // only a handful of times (correctness + capture), so the leak is bounded.
}

// round 10
// speedup vs baseline: 6.5201x; 1.2136x over previous
#include <cuda_runtime.h>
#include <cuda_fp16.h>
#include <math.h>
#include <stdint.h>

#define BB 1024
#define DD 512
#define KK 255
#define LL 256
#define CC 80
#define NGRP 16

#define WCH 11520      // W chunk: 80 rows x 144B (fp16)
#define XCH 18432      // X chunk: 128 rows x 144B (fp16)
#define NECH 9216      // ne chunk: 64 rows x 144B (fp16)

// ---- smem layout for k_main (bytes) ----
#define SM_X   0                     // 8 chunks x 18432 = 147456 (X resident)
#define SM_W   147456                // 4 bufs x 11520 = 46080
#define SM_PS  193536                // 128*17*4 = 8704
#define SM_BS  202240                // 16*80*4 = 5120
#define SM_MB  207360                // mbarriers (128B)
#define SMEM_MAIN 207488

// ---- smem layout for k_nsim ----
#define NS_X   0                     // 2 bufs x (xh 18432 + xl 18432) = 73728
#define NS_NE  73728                 // neh 4x9216 then nel 4x9216 = 73728
#define NS_MB  147456
#define SMEM_NS 147584

// ---------------- device scratch ----------------
__device__ float g_probs[BB * LL];
__device__ float g_partial[NGRP * BB * CC];
__device__ float g_zp[2 * BB * 256];                            // nodesim k-split partials
__device__ __align__(16) uint8_t g_wb[(size_t)LL * 8 * WCH];    // [leaf][ks][80x144B] fp16
__device__ __align__(16) uint8_t g_xb[(size_t)8 * 8 * XCH];     // [rt][ks][128x144B] fp16 hi
__device__ __align__(16) uint8_t g_xl[(size_t)8 * 8 * XCH];     // fp16 lo residual
__device__ __align__(16) uint8_t g_neh[(size_t)4 * 8 * NECH];   // [cg][ks][64x144B] fp16 hi (row255=0)
__device__ __align__(16) uint8_t g_nel[(size_t)4 * 8 * NECH];   // fp16 lo residual

// ---------------- helpers ----------------
__device__ __forceinline__ uint32_t s2u(const void* p) {
    uint32_t a;
    asm("{ .reg .u64 t; cvta.to.shared.u64 t, %1; cvt.u32.u64 %0, t; }" : "=r"(a) : "l"(p));
    return a;
}
#define MBINIT(m, c)  asm volatile("mbarrier.init.shared.b64 [%0], %1;" :: "r"(m), "r"(c) : "memory")
#define MBEXPECT(m, b) asm volatile("mbarrier.arrive.expect_tx.shared.b64 _, [%0], %1;" :: "r"(m), "r"(b) : "memory")
#define MBARRIVE(m)   asm volatile("mbarrier.arrive.shared.b64 _, [%0];" :: "r"(m) : "memory")
__device__ __forceinline__ void mbwait(uint32_t m, uint32_t ph) {
    asm volatile(
        "{\n .reg .pred P;\n"
        "LW_%=:\n mbarrier.try_wait.parity.acquire.cta.shared::cta.b64 P, [%0], %1, 0x989680;\n"
        " @P bra LD_%=;\n bra LW_%=;\nLD_%=:\n}"
        :: "r"(m), "r"(ph) : "memory");
}
#define BULK(dst, src, sz, mb) \
    asm volatile("cp.async.bulk.shared::cta.global.mbarrier::complete_tx::bytes [%0], [%1], %2, [%3];" \
                 :: "r"(dst), "l"(src), "r"(sz), "r"(mb) : "memory")

__device__ __forceinline__ void ldsm4(uint32_t* r, uint32_t a) {
    asm volatile("ldmatrix.sync.aligned.m8n8.x4.shared.b16 {%0,%1,%2,%3}, [%4];"
        : "=r"(r[0]), "=r"(r[1]), "=r"(r[2]), "=r"(r[3]) : "r"(a));
}
__device__ __forceinline__ void ldsm2(uint32_t* r, uint32_t a) {
    asm volatile("ldmatrix.sync.aligned.m8n8.x2.shared.b16 {%0,%1}, [%2];"
        : "=r"(r[0]), "=r"(r[1]) : "r"(a));
}
__device__ __forceinline__ void mma_f16(float* c, const uint32_t* a, const uint32_t* b) {
    asm volatile(
        "mma.sync.aligned.m16n8k16.row.col.f32.f16.f16.f32 "
        "{%0,%1,%2,%3}, {%4,%5,%6,%7}, {%8,%9}, {%0,%1,%2,%3};"
        : "+f"(c[0]), "+f"(c[1]), "+f"(c[2]), "+f"(c[3])
        : "r"(a[0]), "r"(a[1]), "r"(a[2]), "r"(a[3]), "r"(b[0]), "r"(b[1]));
}

// ---------------- K1: normalize node embeddings -> fp16 hi/lo MMA layout ----------------
__global__ void k_norm(const float* __restrict__ ne) {
    int k = blockIdx.x;              // 0..254
    int t = threadIdx.x;             // 128
    const float* row = ne + (size_t)k * DD;
    float4 v = *(const float4*)(row + t * 4);
    float s = v.x * v.x + v.y * v.y + v.z * v.z + v.w * v.w;
    __shared__ float red[4];
    #pragma unroll
    for (int o = 16; o > 0; o >>= 1) s += __shfl_xor_sync(0xffffffffu, s, o);
    if ((t & 31) == 0) red[t >> 5] = s;
    __syncthreads();
    float inv = 1.0f / sqrtf(red[0] + red[1] + red[2] + red[3]);
    float vv[4] = {v.x * inv, v.y * inv, v.z * inv, v.w * inv};
    unsigned short hb[4], lb[4];
    #pragma unroll
    for (int i = 0; i < 4; ++i) {
        __half h = __float2half_rn(vv[i]);
        hb[i] = __half_as_ushort(h);
        lb[i] = __half_as_ushort(__float2half_rn(vv[i] - __half2float(h)));
    }
    int d0 = t * 4, ks = d0 >> 6, k8 = d0 & 63;
    int cg = k >> 6, r = k & 63;
    size_t off = (size_t)(cg * 8 + ks) * NECH + r * 144 + k8 * 2;
    *(uint2*)(g_neh + off) = make_uint2(((uint32_t)hb[1] << 16) | hb[0], ((uint32_t)hb[3] << 16) | hb[2]);
    *(uint2*)(g_nel + off) = make_uint2(((uint32_t)lb[1] << 16) | lb[0], ((uint32_t)lb[3] << 16) | lb[2]);
}

// ---------------- K2: node_sim logits via HMMA 3-term, k-split=2 ----------------
// grid (8 rt, 4 cg, 2 z), 256 threads = 8 warps (4M x 2N); warp tile 32x32.
__global__ void __launch_bounds__(256, 1) k_nsim() {
    extern __shared__ char smem[];
    const uint32_t sb = s2u(smem);
    const int tid = threadIdx.x;
    const int rt = blockIdx.x, cg = blockIdx.y, z = blockIdx.z;
    const int wid = tid >> 5, lane = tid & 31;
    const int wm = wid >> 1, wn = wid & 1;
    const int lr = lane >> 2, lc = lane & 3;

    const uint32_t MB = sb + NS_MB;
    #define NXFULL(b)  (MB + (b) * 8)
    #define NXEMPTY(b) (MB + 16 + (b) * 8)
    #define NEFULL     (MB + 32)
    if (tid == 0) {
        for (int b = 0; b < 2; ++b) { MBINIT(NXFULL(b), 1); MBINIT(NXEMPTY(b), 8); }
        MBINIT(NEFULL, 1);
    }
    __syncthreads();

    if (tid == 0) {
        MBEXPECT(NEFULL, 8 * NECH);
        #pragma unroll
        for (int kl = 0; kl < 4; ++kl) {
            size_t src = (size_t)(cg * 8 + z * 4 + kl) * NECH;
            BULK(sb + NS_NE + kl * NECH, g_neh + src, NECH, NEFULL);
            BULK(sb + NS_NE + 36864 + kl * NECH, g_nel + src, NECH, NEFULL);
        }
        #pragma unroll
        for (int b = 0; b < 2; ++b) {
            size_t src = (size_t)(rt * 8 + z * 4 + b) * XCH;
            MBEXPECT(NXFULL(b), 2 * XCH);
            BULK(sb + NS_X + b * 36864, g_xb + src, XCH, NXFULL(b));
            BULK(sb + NS_X + b * 36864 + XCH, g_xl + src, XCH, NXFULL(b));
        }
    }

    const uint32_t aoff0 = (uint32_t)(wm * 32 + ((lane >> 3) & 1) * 8 + (lane & 7)) * 144
                           + ((lane >> 4) & 1) * 16;
    const uint32_t aoff1 = aoff0 + 16 * 144;
    const uint32_t boff0 = (uint32_t)(wn * 32 + ((lane >> 4) & 1) * 8 + (lane & 7)) * 144
                           + ((lane >> 3) & 1) * 16;
    const uint32_t boff1 = boff0 + 16 * 144;

    float acc[2][4][4] = {};
    mbwait(NEFULL, 0);

    for (int kl = 0; kl < 4; ++kl) {
        const int buf = kl & 1;
        mbwait(NXFULL(buf), (kl >> 1) & 1);
        const uint32_t xh = sb + NS_X + buf * 36864;
        const uint32_t xl = xh + XCH;
        const uint32_t nh = sb + NS_NE + kl * NECH;
        const uint32_t nl = nh + 36864;

        #pragma unroll
        for (int kc = 0; kc < 4; ++kc) {
            const int ko = kc * 32;
            uint32_t ah[2][4], al[2][4], bh[4][2], bl[4][2];
            ldsm4(ah[0], xh + aoff0 + ko);
            ldsm4(ah[1], xh + aoff1 + ko);
            ldsm4(al[0], xl + aoff0 + ko);
            ldsm4(al[1], xl + aoff1 + ko);
            ldsm4(&bh[0][0], nh + boff0 + ko);
            ldsm4(&bh[2][0], nh + boff1 + ko);
            ldsm4(&bl[0][0], nl + boff0 + ko);
            ldsm4(&bl[2][0], nl + boff1 + ko);
            #pragma unroll
            for (int mt = 0; mt < 2; ++mt)
                #pragma unroll
                for (int nt = 0; nt < 4; ++nt) {
                    mma_f16(acc[mt][nt], ah[mt], bh[nt]);
                    mma_f16(acc[mt][nt], al[mt], bh[nt]);
                    mma_f16(acc[mt][nt], ah[mt], bl[nt]);
                }
        }
        if (lane == 0) MBARRIVE(NXEMPTY(buf));
        if (tid == 0 && kl + 2 < 4) {
            mbwait(NXEMPTY(buf), (kl >> 1) & 1);
            size_t src = (size_t)(rt * 8 + z * 4 + kl + 2) * XCH;
            MBEXPECT(NXFULL(buf), 2 * XCH);
            BULK(sb + NS_X + buf * 36864, g_xb + src, XCH, NXFULL(buf));
            BULK(sb + NS_X + buf * 36864 + XCH, g_xl + src, XCH, NXFULL(buf));
        }
    }

    float* zp = g_zp + (size_t)z * BB * 256;
    #pragma unroll
    for (int mt = 0; mt < 2; ++mt) {
        int r0 = rt * 128 + wm * 32 + mt * 16 + lr;
        #pragma unroll
        for (int nt = 0; nt < 4; ++nt) {
            int c0 = cg * 64 + wn * 32 + nt * 8 + lc * 2;
            *(float2*)(zp + (size_t)r0 * 256 + c0) = make_float2(acc[mt][nt][0], acc[mt][nt][1]);
            *(float2*)(zp + (size_t)(r0 + 8) * 256 + c0) = make_float2(acc[mt][nt][2], acc[mt][nt][3]);
        }
    }
}

// ---------------- K3: combine partials, sigmoid, leaf probabilities ----------------
__global__ void k_probs(float* __restrict__ out_ns) {
    int b = blockIdx.x;
    int t = threadIdx.x;
    __shared__ float s[KK];
    if (t < KK) {
        float zv = g_zp[(size_t)b * 256 + t] + g_zp[(size_t)BB * 256 + b * 256 + t];
        float sig = 1.0f / (1.0f + expf(-zv));
        s[t] = sig;
        out_ns[(size_t)b * KK + t] = sig;
    }
    __syncthreads();
    float p = 1.0f; int node = 0;
    #pragma unroll
    for (int d = 0; d < 8; ++d) {
        int bit = (t >> (7 - d)) & 1;
        float v = s[node];
        p *= bit ? (1.0f - v) : v;
        node = 2 * node + 1 + bit;
    }
    g_probs[(size_t)b * LL + t] = p;
}

// ---------------- conversion kernels ----------------
__global__ void k_convW(const float* __restrict__ W) {
    int t = blockIdx.x * 256 + threadIdx.x;      // 20480*64
    int row = t >> 6;
    int kg = t & 63;
    int leaf = row / 80, n = row - leaf * 80;
    int ks = kg >> 3, k8 = kg & 7;
    float4 a = *(const float4*)(W + (size_t)row * 512 + kg * 8);
    float4 b = *(const float4*)(W + (size_t)row * 512 + kg * 8 + 4);
    float v[8] = {a.x, a.y, a.z, a.w, b.x, b.y, b.z, b.w};
    unsigned short hb[8];
    #pragma unroll
    for (int i = 0; i < 8; ++i) hb[i] = __half_as_ushort(__float2half_rn(v[i]));
    uint4 HI = make_uint4(((uint32_t)hb[1] << 16) | hb[0], ((uint32_t)hb[3] << 16) | hb[2],
                          ((uint32_t)hb[5] << 16) | hb[4], ((uint32_t)hb[7] << 16) | hb[6]);
    *(uint4*)(g_wb + (size_t)(leaf * 8 + ks) * WCH + n * 144 + k8 * 16) = HI;
}
__global__ void k_convX(const float* __restrict__ x) {
    int t = blockIdx.x * 256 + threadIdx.x;      // 1024*64
    int row = t >> 6;
    int kg = t & 63;
    int rt = row >> 7, r = row & 127;
    int ks = kg >> 3, k8 = kg & 7;
    float4 a = *(const float4*)(x + (size_t)row * 512 + kg * 8);
    float4 b = *(const float4*)(x + (size_t)row * 512 + kg * 8 + 4);
    float v[8] = {a.x, a.y, a.z, a.w, b.x, b.y, b.z, b.w};
    unsigned short hb[8], lb[8];
    #pragma unroll
    for (int i = 0; i < 8; ++i) {
        __half h = __float2half_rn(v[i]);
        hb[i] = __half_as_ushort(h);
        lb[i] = __half_as_ushort(__float2half_rn(v[i] - __half2float(h)));
    }
    size_t off = (size_t)(rt * 8 + ks) * XCH + r * 144 + k8 * 16;
    *(uint4*)(g_xb + off) = make_uint4(((uint32_t)hb[1] << 16) | hb[0], ((uint32_t)hb[3] << 16) | hb[2],
                                       ((uint32_t)hb[5] << 16) | hb[4], ((uint32_t)hb[7] << 16) | hb[6]);
    *(uint4*)(g_xl + off) = make_uint4(((uint32_t)lb[1] << 16) | lb[0], ((uint32_t)lb[3] << 16) | lb[2],
                                       ((uint32_t)lb[5] << 16) | lb[4], ((uint32_t)lb[7] << 16) | lb[6]);
}

// ---------------- K5: main HMMA kernel (leaf-outer, X resident) ----------------
__global__ void __launch_bounds__(256, 1) k_main(const float* __restrict__ bias) {
    extern __shared__ char smem[];
    const uint32_t sb = s2u(smem);
    const int tid = threadIdx.x;
    const int rt = blockIdx.x, grp = blockIdx.y;
    const int wid = tid >> 5, lane = tid & 31;
    const int wm = wid >> 1, wn = wid & 1;
    const int lr = lane >> 2, lc = lane & 3;

    const uint32_t MB = sb + SM_MB;
    #define WFULL(b)  (MB + (b) * 8)
    #define WEMPTY(b) (MB + 32 + (b) * 8)
    #define XFULL     (MB + 64)

    if (tid == 0) {
        for (int b = 0; b < 4; ++b) { MBINIT(WFULL(b), 1); MBINIT(WEMPTY(b), 8); }
        MBINIT(XFULL, 1);
    }
    float* psm = (float*)(smem + SM_PS);
    float* bsm = (float*)(smem + SM_BS);
    for (int j = tid; j < 128 * 16; j += 256) {
        int r = j >> 4, l = j & 15;
        psm[r * 17 + l] = g_probs[(size_t)(rt * 128 + r) * LL + grp * 16 + l];
    }
    for (int j = tid; j < 16 * CC; j += 256) bsm[j] = bias[grp * 16 * CC + j];
    __syncthreads();

    if (tid == 0) {
        MBEXPECT(XFULL, 8 * XCH);
        #pragma unroll
        for (int j = 0; j < 8; ++j)
            BULK(sb + SM_X + j * XCH, g_xb + (size_t)(rt * 8 + j) * XCH, XCH, XFULL);
        #pragma unroll
        for (int s = 0; s < 3; ++s) {
            MBEXPECT(WFULL(s), WCH);
            BULK(sb + SM_W + s * WCH,
                 g_wb + (size_t)(grp * 16 * 8 + s) * WCH, WCH, WFULL(s));
        }
    }

    const uint32_t aoff0 = (uint32_t)(wm * 32 + ((lane >> 3) & 1) * 8 + (lane & 7)) * 144
                           + ((lane >> 4) & 1) * 16;
    const uint32_t aoff1 = aoff0 + 16 * 144;
    const uint32_t boff0 = (uint32_t)(wn * 40 + ((lane >> 4) & 1) * 8 + (lane & 7)) * 144
                           + ((lane >> 3) & 1) * 16;
    const uint32_t boff1 = boff0 + 16 * 144;
    const int l16 = lane & 15;
    const uint32_t boff2 = (uint32_t)(wn * 40 + 32 + (l16 & 7)) * 144 + ((l16 >> 3) & 1) * 16;

    float per[2][5][4] = {};
    int cwf[4] = {0, 0, 0, 0}, pwe[4] = {0, 0, 0, 0};

    mbwait(XFULL, 0);

    for (int leaf = 0; leaf < 16; ++leaf) {
        float acc[2][5][4];
        #pragma unroll
        for (int nt = 0; nt < 5; ++nt) {
            int c0 = wn * 40 + nt * 8 + lc * 2;
            float b0 = bsm[leaf * CC + c0], b1 = bsm[leaf * CC + c0 + 1];
            #pragma unroll
            for (int mt = 0; mt < 2; ++mt) {
                acc[mt][nt][0] = b0; acc[mt][nt][1] = b1;
                acc[mt][nt][2] = b0; acc[mt][nt][3] = b1;
            }
        }

        for (int ks = 0; ks < 8; ++ks) {
            const int s = leaf * 8 + ks, b = s & 3;

            if (tid == 0) {
                int sn = s + 3;
                if (sn < 128) {
                    int bn = sn & 3;
                    if (sn >= 4) { mbwait(WEMPTY(bn), pwe[bn] & 1); pwe[bn]++; }
                    MBEXPECT(WFULL(bn), WCH);
                    BULK(sb + SM_W + bn * WCH,
                         g_wb + (size_t)(grp * 16 * 8 + sn) * WCH, WCH, WFULL(bn));
                }
            }

            mbwait(WFULL(b), cwf[b] & 1); cwf[b]++;
            const uint32_t xk = sb + SM_X + ks * XCH;
            const uint32_t wh = sb + SM_W + b * WCH;

            #pragma unroll
            for (int kc = 0; kc < 4; ++kc) {
                const int ko = kc * 32;
                uint32_t ah[2][4], bh[5][2];
                ldsm4(ah[0], xk + aoff0 + ko);
                ldsm4(ah[1], xk + aoff1 + ko);
                ldsm4(&bh[0][0], wh + boff0 + ko);
                ldsm4(&bh[2][0], wh + boff1 + ko);
                ldsm2(&bh[4][0], wh + boff2 + ko);
                #pragma unroll
                for (int mt = 0; mt < 2; ++mt)
                    #pragma unroll
                    for (int nt = 0; nt < 5; ++nt)
                        mma_f16(acc[mt][nt], ah[mt], bh[nt]);
            }

            if (lane == 0) MBARRIVE(WEMPTY(b));
        }

        #pragma unroll
        for (int mt = 0; mt < 2; ++mt) {
            float p0 = psm[(wm * 32 + mt * 16 + lr) * 17 + leaf];
            float p1 = psm[(wm * 32 + mt * 16 + 8 + lr) * 17 + leaf];
            #pragma unroll
            for (int nt = 0; nt < 5; ++nt) {
                per[mt][nt][0] = fmaf(p0, acc[mt][nt][0], per[mt][nt][0]);
                per[mt][nt][1] = fmaf(p0, acc[mt][nt][1], per[mt][nt][1]);
                per[mt][nt][2] = fmaf(p1, acc[mt][nt][2], per[mt][nt][2]);
                per[mt][nt][3] = fmaf(p1, acc[mt][nt][3], per[mt][nt][3]);
            }
        }
    }

    float* base = g_partial + (size_t)grp * BB * CC;
    #pragma unroll
    for (int mt = 0; mt < 2; ++mt) {
        int r0 = rt * 128 + wm * 32 + mt * 16 + lr;
        #pragma unroll
        for (int nt = 0; nt < 5; ++nt) {
            int c0 = wn * 40 + nt * 8 + lc * 2;
            *(float2*)(base + (size_t)r0 * CC + c0) = make_float2(per[mt][nt][0], per[mt][nt][1]);
            *(float2*)(base + (size_t)(r0 + 8) * CC + c0) = make_float2(per[mt][nt][2], per[mt][nt][3]);
        }
    }
}

// ---------------- K6: reduce partials ----------------
__global__ void k_reduce(float* __restrict__ out) {
    int idx = blockIdx.x * 256 + threadIdx.x;
    float s = 0.f;
    #pragma unroll
    for (int g = 0; g < NGRP; ++g)
        s += g_partial[(size_t)g * BB * CC + idx];
    out[idx] = s;
}

// ---------------- launch (fork/join multi-stream) ----------------
extern "C" void kernel_launch(void* const* d_in, const int* in_sizes, int n_in,
                              void* d_out, int out_size) {
    const float* x    = (const float*)d_in[0];
    const float* ne   = (const float*)d_in[1];
    const float* W    = (const float*)d_in[2];
    const float* bias = (const float*)d_in[3];

    float* out1 = (float*)d_out;
    float* ns   = (float*)d_out + BB * CC;

    cudaFuncSetAttribute(k_main, cudaFuncAttributeMaxDynamicSharedMemorySize, SMEM_MAIN);
    cudaFuncSetAttribute(k_nsim, cudaFuncAttributeMaxDynamicSharedMemorySize, SMEM_NS);

    cudaStream_t s2;
    cudaEvent_t eFork, eJoin;
    cudaStreamCreateWithFlags(&s2, cudaStreamNonBlocking);
    cudaEventCreateWithFlags(&eFork, cudaEventDisableTiming);
    cudaEventCreateWithFlags(&eJoin, cudaEventDisableTiming);

    cudaEventRecord(eFork, 0);
    cudaStreamWaitEvent(s2, eFork, 0);

    // branch A (side stream): W conversion
    k_convW<<<5120, 256, 0, s2>>>(W);
    cudaEventRecord(eJoin, s2);

    // branch B (main stream): x conversion -> ne norm -> node-sim HMMA -> probs
    k_convX<<<256, 256>>>(x);
    k_norm<<<KK, 128>>>(ne);
    dim3 gn(8, 4, 2);
    k_nsim<<<gn, 256, SMEM_NS>>>();
    k_probs<<<BB, 256>>>(ns);

    cudaStreamWaitEvent(0, eJoin, 0);
    dim3 g5(8, NGRP);
    k_main<<<g5, 256, SMEM_MAIN>>>(bias);
    k_reduce<<<(BB * CC) / 256, 256>>>(out1);

    // note: s2/eFork/eJoin intentionally not destroyed — destroying
    // capture-referenced handles mid-capture is UB; bounded leak.
}